// round 13
// baseline (speedup 1.0000x reference)
#include <cuda_runtime.h>
#include <cuda_bf16.h>
#include <math.h>
#include <cstdint>

#define NLAYER 6
#define DV     512
#define NH     8
#define HD     64
#define DFF    2048
#define BB     8
#define LL     1024
#define MM     (BB*LL)
#define QKV_STRIDE (3*DV)

// ---------------- scratch ----------------
__device__ float g_out [MM*DV];
__device__ float g_tmp [MM*DV];
__device__ unsigned char g_kpm[MM];

#define W_IN_SZ   (NLAYER*3*DV*DV)
#define W_OUT_SZ  (NLAYER*DV*DV)
#define W_L1_SZ   (NLAYER*DFF*DV)
#define W_L2_SZ   (NLAYER*DV*DFF)
#define W_TOT     (W_IN_SZ+W_OUT_SZ+W_L1_SZ+W_L2_SZ)
#define OFF_IN    0
#define OFF_OUT   (W_IN_SZ)
#define OFF_L1    (W_IN_SZ+W_OUT_SZ)
#define OFF_L2    (W_IN_SZ+W_OUT_SZ+W_L1_SZ)
__device__ __nv_bfloat16 g_whib[W_TOT];
__device__ __nv_bfloat16 g_wlob[W_TOT];
__device__ __nv_bfloat16 g_ahib[MM*DFF];
__device__ __nv_bfloat16 g_alob[MM*DFF];
__device__ __nv_bfloat16 g_hhib[MM*DFF];
__device__ __nv_bfloat16 g_hlob[MM*DFF];
__device__ __nv_bfloat16 g_qkvh[MM*3*DV];
__device__ __nv_bfloat16 g_qkvl[MM*3*DV];

// ---------------- smem / mma helpers ----------------
__device__ __forceinline__ uint32_t s2u(const void* p) {
    uint32_t a;
    asm("{ .reg .u64 t; cvta.to.shared.u64 t, %1; cvt.u32.u64 %0, t; }" : "=r"(a) : "l"(p));
    return a;
}
__device__ __forceinline__ void cpa16(uint32_t dst, const void* src) {
    asm volatile("cp.async.cg.shared.global [%0], [%1], 16;" :: "r"(dst), "l"(src) : "memory");
}
__device__ __forceinline__ void cpa_commit() { asm volatile("cp.async.commit_group;" ::: "memory"); }
__device__ __forceinline__ void cpa_wait0() { asm volatile("cp.async.wait_group 0;" ::: "memory"); }
__device__ __forceinline__ void cpa_wait1() { asm volatile("cp.async.wait_group 1;" ::: "memory"); }
__device__ __forceinline__ void ldmx4(uint32_t* r, uint32_t addr) {
    asm volatile("ldmatrix.sync.aligned.m8n8.x4.shared.b16 {%0,%1,%2,%3}, [%4];"
        : "=r"(r[0]), "=r"(r[1]), "=r"(r[2]), "=r"(r[3]) : "r"(addr));
}
__device__ __forceinline__ void ldmx4t(uint32_t* r, uint32_t addr) {
    asm volatile("ldmatrix.sync.aligned.m8n8.x4.trans.shared.b16 {%0,%1,%2,%3}, [%4];"
        : "=r"(r[0]), "=r"(r[1]), "=r"(r[2]), "=r"(r[3]) : "r"(addr));
}
__device__ __forceinline__ void mma_bf16(float* d, const uint32_t* a, const uint32_t* b) {
    asm volatile("mma.sync.aligned.m16n8k16.row.col.f32.bf16.bf16.f32 "
        "{%0,%1,%2,%3}, {%4,%5,%6,%7}, {%8,%9}, {%0,%1,%2,%3};"
        : "+f"(d[0]), "+f"(d[1]), "+f"(d[2]), "+f"(d[3])
        : "r"(a[0]), "r"(a[1]), "r"(a[2]), "r"(a[3]), "r"(b[0]), "r"(b[1]));
}
__device__ __forceinline__ float ex2f(float x) {
    float r;
    asm("ex2.approx.f32 %0, %1;" : "=f"(r) : "f"(x));
    return r;
}

// hi/lo bf16x2 pair from two floats (x0 -> low half)
#define CVTPAIR(dsthi, dstlo, x0, x1) do { \
    uint32_t _hp; asm("cvt.rn.bf16x2.f32 %0, %1, %2;" : "=r"(_hp) : "f"(x1), "f"(x0)); \
    float _h0 = __uint_as_float(_hp << 16); \
    float _h1 = __uint_as_float(_hp & 0xFFFF0000u); \
    uint32_t _lp; asm("cvt.rn.bf16x2.f32 %0, %1, %2;" : "=r"(_lp) : "f"((x1) - _h1), "f"((x0) - _h0)); \
    (dsthi) = _hp; (dstlo) = _lp; } while(0)

// ---------------- key padding mask ----------------
__global__ void kpm_kernel(const float* __restrict__ x, unsigned char* __restrict__ kpm)
{
    int row = blockIdx.x;
    int t = threadIdx.x;
    int nz = 0;
    for (int c = t; c < DV; c += 128)
        nz |= (x[(size_t)row * DV + c] != 0.0f) ? 1 : 0;
    nz = __syncthreads_or(nz);
    if (t == 0) kpm[row] = nz ? 0 : 1;
}

// ---------------- copy + hi/lo split (initial x) ----------------
__global__ void copy_split_kernel(const float* __restrict__ src, float* __restrict__ dst,
                                  __nv_bfloat16* __restrict__ hi, __nv_bfloat16* __restrict__ lo, int n4)
{
    int i = blockIdx.x * blockDim.x + threadIdx.x;
    if (i >= n4) return;
    float4 v = ((const float4*)src)[i];
    ((float4*)dst)[i] = v;
    __nv_bfloat16 h0 = __float2bfloat16_rn(v.x), h1 = __float2bfloat16_rn(v.y);
    __nv_bfloat16 h2 = __float2bfloat16_rn(v.z), h3 = __float2bfloat16_rn(v.w);
    __nv_bfloat162* hp = (__nv_bfloat162*)hi;
    __nv_bfloat162* lp = (__nv_bfloat162*)lo;
    hp[2*i]   = __nv_bfloat162(h0, h1);
    hp[2*i+1] = __nv_bfloat162(h2, h3);
    lp[2*i]   = __nv_bfloat162(__float2bfloat16_rn(v.x - __bfloat162float(h0)),
                               __float2bfloat16_rn(v.y - __bfloat162float(h1)));
    lp[2*i+1] = __nv_bfloat162(__float2bfloat16_rn(v.z - __bfloat162float(h2)),
                               __float2bfloat16_rn(v.w - __bfloat162float(h3)));
}

// ---------------- weight hi/lo split ----------------
__global__ void splitb_kernel(const float* __restrict__ src,
                              __nv_bfloat16* __restrict__ hi,
                              __nv_bfloat16* __restrict__ lo, int n4)
{
    int i = blockIdx.x * blockDim.x + threadIdx.x;
    if (i >= n4) return;
    float4 v = ((const float4*)src)[i];
    __nv_bfloat16 h0 = __float2bfloat16_rn(v.x), h1 = __float2bfloat16_rn(v.y);
    __nv_bfloat16 h2 = __float2bfloat16_rn(v.z), h3 = __float2bfloat16_rn(v.w);
    __nv_bfloat162* hp = (__nv_bfloat162*)hi;
    __nv_bfloat162* lp = (__nv_bfloat162*)lo;
    hp[2*i]   = __nv_bfloat162(h0, h1);
    hp[2*i+1] = __nv_bfloat162(h2, h3);
    lp[2*i]   = __nv_bfloat162(__float2bfloat16_rn(v.x - __bfloat162float(h0)),
                               __float2bfloat16_rn(v.y - __bfloat162float(h1)));
    lp[2*i+1] = __nv_bfloat162(__float2bfloat16_rn(v.z - __bfloat162float(h2)),
                               __float2bfloat16_rn(v.w - __bfloat162float(h3)));
}

// ---------------- HMMA bf16 hi/lo GEMM (3-stage cp.async, 1 barrier/chunk) ----------------
#define GSM_STAGE 32768
#define GSM_TOTAL (3*GSM_STAGE)

__device__ __forceinline__ uint32_t swz(int row, int kch) {
    return (uint32_t)(row * 64 + (((kch + ((row >> 1) & 3)) & 3) << 4));
}

template<bool GELU, bool SPLIT>
__global__ __launch_bounds__(256) void hmma_gemm(
    const __nv_bfloat16* __restrict__ Ahi, const __nv_bfloat16* __restrict__ Alo,
    const __nv_bfloat16* __restrict__ Whi, const __nv_bfloat16* __restrict__ Wlo,
    const float* __restrict__ bias, float* __restrict__ C,
    __nv_bfloat16* __restrict__ Chi, __nv_bfloat16* __restrict__ Clo,
    int N, int K)
{
    extern __shared__ __align__(16) char sm[];
    const uint32_t sb = s2u(sm);
    const int t = threadIdx.x;
    const int bm = blockIdx.y * 128, bn = blockIdx.x * 128;
    const int w = t >> 5, l = t & 31;
    const int wm = w & 3, wn = w >> 2;

    float acc[2][8][4];
#pragma unroll
    for (int mt = 0; mt < 2; mt++)
#pragma unroll
        for (int nt = 0; nt < 8; nt++)
#pragma unroll
            for (int e = 0; e < 4; e++) acc[mt][nt][e] = 0.0f;

    const int nch = K >> 5;

    auto load_stage = [&](int stage, int kt) {
        const uint32_t base = sb + stage * GSM_STAGE;
        const int k0 = kt << 5;
#pragma unroll
        for (int q = 0; q < 2; q++) {
            int ch = t + (q << 8);
            int row = ch >> 2, c = ch & 3;
            uint32_t so = swz(row, c);
            size_t ga = (size_t)(bm + row) * K + k0 + c * 8;
            size_t gb = (size_t)(bn + row) * K + k0 + c * 8;
            cpa16(base + so,          Ahi + ga);
            cpa16(base + 8192 + so,   Alo + ga);
            cpa16(base + 16384 + so,  Whi + gb);
            cpa16(base + 24576 + so,  Wlo + gb);
        }
        cpa_commit();
    };

    load_stage(0, 0);
    load_stage(1, 1);   // nch >= 16 always here

    int stg = 0;
    for (int c = 0; c < nch; ++c) {
        if (c + 1 < nch) cpa_wait1(); else cpa_wait0();
        __syncthreads();
        if (c + 2 < nch) {
            int ns = stg + 2; if (ns >= 3) ns -= 3;
            load_stage(ns, c + 2);
        }

        const uint32_t base = sb + stg * GSM_STAGE;
#pragma unroll
        for (int kk = 0; kk < 2; kk++) {
            uint32_t ah[2][4], al[2][4];
#pragma unroll
            for (int mt = 0; mt < 2; mt++) {
                int row = wm * 32 + mt * 16 + (l & 15);
                int kch = kk * 2 + (l >> 4);
                uint32_t off = swz(row, kch);
                ldmx4(ah[mt], base + off);
                ldmx4(al[mt], base + 8192 + off);
            }
            uint32_t bh[8][2], bl[8][2];
#pragma unroll
            for (int nt2 = 0; nt2 < 4; nt2++) {
                int row = wn * 64 + nt2 * 16 + (l & 7) + ((l >> 4) << 3);
                int kch = kk * 2 + ((l >> 3) & 1);
                uint32_t off = swz(row, kch);
                uint32_t r[4];
                ldmx4(r, base + 16384 + off);
                bh[nt2*2][0] = r[0]; bh[nt2*2][1] = r[1];
                bh[nt2*2+1][0] = r[2]; bh[nt2*2+1][1] = r[3];
                ldmx4(r, base + 24576 + off);
                bl[nt2*2][0] = r[0]; bl[nt2*2][1] = r[1];
                bl[nt2*2+1][0] = r[2]; bl[nt2*2+1][1] = r[3];
            }
#pragma unroll
            for (int mt = 0; mt < 2; mt++)
#pragma unroll
                for (int nt = 0; nt < 8; nt++) {
                    mma_bf16(acc[mt][nt], ah[mt], bh[nt]);
                    mma_bf16(acc[mt][nt], ah[mt], bl[nt]);
                    mma_bf16(acc[mt][nt], al[mt], bh[nt]);
                }
        }
        if (++stg >= 3) stg = 0;
    }

#pragma unroll
    for (int mt = 0; mt < 2; mt++) {
        int row = bm + wm * 32 + mt * 16 + (l >> 2);
#pragma unroll
        for (int nt = 0; nt < 8; nt++) {
            int col = bn + wn * 64 + nt * 8 + 2 * (l & 3);
            float b0 = bias[col], b1 = bias[col + 1];
            float v0 = acc[mt][nt][0] + b0;
            float v1 = acc[mt][nt][1] + b1;
            float v2 = acc[mt][nt][2] + b0;
            float v3 = acc[mt][nt][3] + b1;
            if (GELU) {
                v0 = 0.5f * v0 * (1.0f + erff(v0 * 0.70710678118654752f));
                v1 = 0.5f * v1 * (1.0f + erff(v1 * 0.70710678118654752f));
                v2 = 0.5f * v2 * (1.0f + erff(v2 * 0.70710678118654752f));
                v3 = 0.5f * v3 * (1.0f + erff(v3 * 0.70710678118654752f));
            }
            if (SPLIT) {
                uint32_t hp, lp;
                CVTPAIR(hp, lp, v0, v1);
                *(uint32_t*)(Chi + (size_t)row * N + col) = hp;
                *(uint32_t*)(Clo + (size_t)row * N + col) = lp;
                CVTPAIR(hp, lp, v2, v3);
                *(uint32_t*)(Chi + (size_t)(row + 8) * N + col) = hp;
                *(uint32_t*)(Clo + (size_t)(row + 8) * N + col) = lp;
            } else {
                *(float2*)(C + (size_t)row * N + col)       = make_float2(v0, v1);
                *(float2*)(C + (size_t)(row + 8) * N + col) = make_float2(v2, v3);
            }
        }
    }
}

// ---------------- mma.sync flash attention (3-stage K/V pipeline, no-max softmax) ----------------
// Scores are bounded (|s| << 30 in log2 domain): skip online max tracking entirely.
// smem: stages 0/1/2 at 0/32768/65536; sbias(log2e-scaled) @98304, smask @102400.
#define ASM_TOTAL 106496

__global__ __launch_bounds__(256, 1) void attn_mma(
    const __nv_bfloat16* __restrict__ qkvh, const __nv_bfloat16* __restrict__ qkvl,
    const float* __restrict__ dist_emb, const unsigned char* __restrict__ kpm,
    __nv_bfloat16* __restrict__ ohi, __nv_bfloat16* __restrict__ olo)
{
    extern __shared__ __align__(16) char sm[];
    const uint32_t sb0 = s2u(sm);
    const int bh = blockIdx.x;
    const int b = bh >> 3, h = bh & 7;
    const int qbi = (int)gridDim.y - 1 - (int)blockIdx.y;   // long blocks first
    const int qbase = qbi * 128;
    const int t = threadIdx.x;
    const int w = t >> 5, l = t & 31;

    const float LOG2E = 1.4426950408889634f;
    float* sbias = (float*)(sm + 98304);
    float* smask = (float*)(sm + 102400);
    for (int d = t; d < LL; d += 256) {
        sbias[d] = dist_emb[d * NH + h] * LOG2E;
        smask[d] = kpm[b * LL + d] ? -2e30f : 0.0f;
    }

    // stage Q (hi @ sb0, lo @ sb0+16384)
#pragma unroll
    for (int q = 0; q < 4; q++) {
        int c = t + q * 256;
        int row = c >> 3, ch = c & 7;
        size_t g = (size_t)(b * LL + qbase + row) * QKV_STRIDE + h * HD + ch * 8;
        uint32_t off = (uint32_t)(row * 128 + ((ch ^ (row & 7)) << 4));
        cpa16(sb0 + off, qkvh + g);
        cpa16(sb0 + 16384 + off, qkvl + g);
    }
    cpa_commit();
    cpa_wait0();
    __syncthreads();

    uint32_t qh[4][4], ql[4][4];
    {
        int qrow = w * 16 + (l & 15);
#pragma unroll
        for (int j = 0; j < 4; j++) {
            int ch = 2 * j + (l >> 4);
            uint32_t addr = sb0 + qrow * 128 + ((ch ^ (qrow & 7)) << 4);
            ldmx4(qh[j], addr);
            ldmx4(ql[j], addr + 16384);
        }
    }
    __syncthreads();   // Q extracted before stage0 K/V overwrite

    float o[8][4];
#pragma unroll
    for (int dt = 0; dt < 8; dt++)
#pragma unroll
        for (int e = 0; e < 4; e++) o[dt][e] = 0.0f;
    float ls0 = 0.0f, ls1 = 0.0f;
    const int i0 = qbase + w * 16 + (l >> 2);
    const int i1 = i0 + 8;
    const int ntile = (qbase + 128) >> 6;

    auto load_kv = [&](int stage, int jt) {
        const uint32_t base = sb0 + stage * 32768;
#pragma unroll
        for (int q = 0; q < 2; q++) {
            int c = t + q * 256;
            int row = c >> 3, ch = c & 7;
            size_t gk = (size_t)(b * LL + jt + row) * QKV_STRIDE + DV + h * HD + ch * 8;
            size_t gv = gk + DV;
            uint32_t off = (uint32_t)(row * 128 + ((ch ^ (row & 7)) << 4));
            cpa16(base + off,          qkvh + gk);
            cpa16(base + 8192 + off,   qkvl + gk);
            cpa16(base + 16384 + off,  qkvh + gv);
            cpa16(base + 24576 + off,  qkvl + gv);
        }
        cpa_commit();
    };

    load_kv(0, 0);
    if (ntile > 1) load_kv(1, 64);

    int stg = 0;
    for (int ti = 0; ti < ntile; ti++) {
        if (ti + 1 < ntile) cpa_wait1(); else cpa_wait0();
        __syncthreads();
        if (ti + 2 < ntile) {
            int ns = stg + 2; if (ns >= 3) ns -= 3;
            load_kv(ns, (ti + 2) << 6);
        }

        const int jt = ti << 6;
        if (jt <= qbase + w * 16 + 15) {
            const uint32_t kb = sb0 + stg * 32768;

            // ---- S = Q K^T (3-term hi/lo) ----
            float s[8][4];
#pragma unroll
            for (int nt = 0; nt < 8; nt++)
#pragma unroll
                for (int e = 0; e < 4; e++) s[nt][e] = 0.0f;

            const int krow = (l & 7) + ((l >> 4) << 3);
#pragma unroll
            for (int kc = 0; kc < 4; kc++) {
                const int kch = 2 * kc + ((l >> 3) & 1);
#pragma unroll
                for (int nt2 = 0; nt2 < 4; nt2++) {
                    int row = nt2 * 16 + krow;
                    uint32_t addr = kb + row * 128 + ((kch ^ (row & 7)) << 4);
                    uint32_t rh[4], rl[4];
                    ldmx4(rh, addr);
                    ldmx4(rl, addr + 8192);
                    uint32_t b0h[2] = {rh[0], rh[1]}, b1h[2] = {rh[2], rh[3]};
                    uint32_t b0l[2] = {rl[0], rl[1]}, b1l[2] = {rl[2], rl[3]};
                    mma_bf16(s[nt2*2],   qh[kc], b0h);
                    mma_bf16(s[nt2*2],   qh[kc], b0l);
                    mma_bf16(s[nt2*2],   ql[kc], b0h);
                    mma_bf16(s[nt2*2+1], qh[kc], b1h);
                    mma_bf16(s[nt2*2+1], qh[kc], b1l);
                    mma_bf16(s[nt2*2+1], ql[kc], b1h);
                }
            }

            // ---- scale(log2) + bias + causal/kpm mask, then direct exp2 ----
            const float scale2 = 0.125f * LOG2E;
            const int jc = jt + 2 * (l & 3);
#pragma unroll
            for (int nt = 0; nt < 8; nt++) {
                int j0 = jc + nt * 8;
                float mk0 = smask[j0], mk1 = smask[j0 + 1];
                int d0 = i0 - j0;
                int d1 = i1 - j0;
                s[nt][0] = (d0 >= 0) ? ex2f(fmaf(s[nt][0], scale2, sbias[d0]     + mk0)) : 0.0f;
                s[nt][1] = (d0 >= 1) ? ex2f(fmaf(s[nt][1], scale2, sbias[d0 - 1] + mk1)) : 0.0f;
                s[nt][2] = (d1 >= 0) ? ex2f(fmaf(s[nt][2], scale2, sbias[d1]     + mk0)) : 0.0f;
                s[nt][3] = (d1 >= 1) ? ex2f(fmaf(s[nt][3], scale2, sbias[d1 - 1] + mk1)) : 0.0f;
                ls0 += s[nt][0] + s[nt][1];
                ls1 += s[nt][2] + s[nt][3];
            }

            // ---- P -> bf16 hi/lo A-fragments ----
            uint32_t ph[4][4], pl[4][4];
#pragma unroll
            for (int j = 0; j < 4; j++) {
                CVTPAIR(ph[j][0], pl[j][0], s[2*j][0],   s[2*j][1]);
                CVTPAIR(ph[j][1], pl[j][1], s[2*j][2],   s[2*j][3]);
                CVTPAIR(ph[j][2], pl[j][2], s[2*j+1][0], s[2*j+1][1]);
                CVTPAIR(ph[j][3], pl[j][3], s[2*j+1][2], s[2*j+1][3]);
            }

            // ---- O += P V (3-term) ----
            const int vsub = (l & 7) + (((l >> 3) & 1) << 3);
#pragma unroll
            for (int j = 0; j < 4; j++) {
                int vrow = j * 16 + vsub;
#pragma unroll
                for (int dp = 0; dp < 4; dp++) {
                    int ch = 2 * dp + (l >> 4);
                    uint32_t addr = kb + 16384 + vrow * 128 + ((ch ^ (vrow & 7)) << 4);
                    uint32_t rh[4], rl[4];
                    ldmx4t(rh, addr);
                    ldmx4t(rl, addr + 8192);
                    uint32_t v0h[2] = {rh[0], rh[1]}, v1h[2] = {rh[2], rh[3]};
                    uint32_t v0l[2] = {rl[0], rl[1]}, v1l[2] = {rl[2], rl[3]};
                    mma_bf16(o[2*dp],   ph[j], v0h);
                    mma_bf16(o[2*dp],   pl[j], v0h);
                    mma_bf16(o[2*dp],   ph[j], v0l);
                    mma_bf16(o[2*dp+1], ph[j], v1h);
                    mma_bf16(o[2*dp+1], pl[j], v1h);
                    mma_bf16(o[2*dp+1], ph[j], v1l);
                }
            }
        }
        if (++stg >= 3) stg = 0;
    }

    // ---- finalize ----
    ls0 += __shfl_xor_sync(0xFFFFFFFFu, ls0, 1);
    ls0 += __shfl_xor_sync(0xFFFFFFFFu, ls0, 2);
    ls1 += __shfl_xor_sync(0xFFFFFFFFu, ls1, 1);
    ls1 += __shfl_xor_sync(0xFFFFFFFFu, ls1, 2);
    float inv0 = 1.0f / ls0, inv1 = 1.0f / ls1;

#pragma unroll
    for (int dt = 0; dt < 8; dt++) {
        int col = h * HD + dt * 8 + 2 * (l & 3);
        size_t r0 = (size_t)(b * LL + i0) * DV + col;
        size_t r1 = (size_t)(b * LL + i1) * DV + col;
        uint32_t hp, lp;
        CVTPAIR(hp, lp, o[dt][0] * inv0, o[dt][1] * inv0);
        *(uint32_t*)(ohi + r0) = hp;
        *(uint32_t*)(olo + r0) = lp;
        CVTPAIR(hp, lp, o[dt][2] * inv1, o[dt][3] * inv1);
        *(uint32_t*)(ohi + r1) = hp;
        *(uint32_t*)(olo + r1) = lp;
    }
}

// ---------------- residual + LayerNorm (float4-vectorized, optional bf16 hi/lo out) ----------------
__global__ __launch_bounds__(128) void ln_kernel(
    const float* __restrict__ x, const float* __restrict__ res,
    const float* __restrict__ g, const float* __restrict__ beta,
    float* __restrict__ outp,
    __nv_bfloat16* __restrict__ ohi, __nv_bfloat16* __restrict__ olo)
{
    const int row = blockIdx.x;
    const int t = threadIdx.x;
    const size_t base = (size_t)row * DV + 4 * t;

    float4 v = *(const float4*)(x + base);
    if (res) {
        float4 rv = *(const float4*)(res + base);
        v.x += rv.x; v.y += rv.y; v.z += rv.z; v.w += rv.w;
    }
    float s  = v.x + v.y + v.z + v.w;
    float ss = v.x * v.x + v.y * v.y + v.z * v.z + v.w * v.w;
#pragma unroll
    for (int o = 16; o > 0; o >>= 1) {
        s  += __shfl_xor_sync(0xFFFFFFFFu, s,  o);
        ss += __shfl_xor_sync(0xFFFFFFFFu, ss, o);
    }
    __shared__ float rs[4], rss[4];
    int w = t >> 5;
    if ((t & 31) == 0) { rs[w] = s; rss[w] = ss; }
    __syncthreads();
    s  = rs[0] + rs[1] + rs[2] + rs[3];
    ss = rss[0] + rss[1] + rss[2] + rss[3];
    float mean = s * (1.0f / DV);
    float var  = ss * (1.0f / DV) - mean * mean;
    float r = rsqrtf(var + 1e-5f);

    float4 gv = *(const float4*)(g + 4 * t);
    float4 bv = *(const float4*)(beta + 4 * t);
    float4 ov;
    ov.x = (v.x - mean) * r * gv.x + bv.x;
    ov.y = (v.y - mean) * r * gv.y + bv.y;
    ov.z = (v.z - mean) * r * gv.z + bv.z;
    ov.w = (v.w - mean) * r * gv.w + bv.w;
    *(float4*)(outp + base) = ov;
    if (ohi) {
        uint32_t hp, lp;
        CVTPAIR(hp, lp, ov.x, ov.y);
        *(uint32_t*)(ohi + base) = hp;
        *(uint32_t*)(olo + base) = lp;
        CVTPAIR(hp, lp, ov.z, ov.w);
        *(uint32_t*)(ohi + base + 2) = hp;
        *(uint32_t*)(olo + base + 2) = lp;
    }
}

// ---------------- host launcher ----------------
extern "C" void kernel_launch(void* const* d_in, const int* in_sizes, int n_in,
                              void* d_out, int out_size)
{
    (void)in_sizes; (void)n_in; (void)out_size;
    const float* x         = (const float*)d_in[0];
    const float* dist_emb  = (const float*)d_in[1];
    const float* in_proj_w = (const float*)d_in[2];
    const float* in_proj_b = (const float*)d_in[3];
    const float* out_w     = (const float*)d_in[4];
    const float* out_b     = (const float*)d_in[5];
    const float* lin1_w    = (const float*)d_in[6];
    const float* lin1_b    = (const float*)d_in[7];
    const float* lin2_w    = (const float*)d_in[8];
    const float* lin2_b    = (const float*)d_in[9];
    const float* ln1_g     = (const float*)d_in[10];
    const float* ln1_bp    = (const float*)d_in[11];
    const float* ln2_g     = (const float*)d_in[12];
    const float* ln2_bp    = (const float*)d_in[13];
    const float* lnf_g     = (const float*)d_in[14];
    const float* lnf_bp    = (const float*)d_in[15];

    float *p_out, *p_tmp;
    __nv_bfloat16 *p_whi, *p_wlo, *p_ahi, *p_alo, *p_hhi, *p_hlo, *p_qkvh, *p_qkvl;
    unsigned char* p_kpm;
    cudaGetSymbolAddress((void**)&p_out,  g_out);
    cudaGetSymbolAddress((void**)&p_tmp,  g_tmp);
    cudaGetSymbolAddress((void**)&p_whi,  g_whib);
    cudaGetSymbolAddress((void**)&p_wlo,  g_wlob);
    cudaGetSymbolAddress((void**)&p_ahi,  g_ahib);
    cudaGetSymbolAddress((void**)&p_alo,  g_alob);
    cudaGetSymbolAddress((void**)&p_hhi,  g_hhib);
    cudaGetSymbolAddress((void**)&p_hlo,  g_hlob);
    cudaGetSymbolAddress((void**)&p_qkvh, g_qkvh);
    cudaGetSymbolAddress((void**)&p_qkvl, g_qkvl);
    cudaGetSymbolAddress((void**)&p_kpm,  g_kpm);

    cudaFuncSetAttribute(hmma_gemm<false,false>, cudaFuncAttributeMaxDynamicSharedMemorySize, GSM_TOTAL);
    cudaFuncSetAttribute(hmma_gemm<false,true>,  cudaFuncAttributeMaxDynamicSharedMemorySize, GSM_TOTAL);
    cudaFuncSetAttribute(hmma_gemm<true,true>,   cudaFuncAttributeMaxDynamicSharedMemorySize, GSM_TOTAL);
    cudaFuncSetAttribute(attn_mma, cudaFuncAttributeMaxDynamicSharedMemorySize, ASM_TOTAL);

    kpm_kernel<<<MM, 128>>>(x, p_kpm);
    {
        int n4 = MM * DV / 4;
        copy_split_kernel<<<(n4 + 255) / 256, 256>>>(x, p_out, p_ahi, p_alo, n4);
    }

    // split weights once
    {
        int n4;
        n4 = W_IN_SZ  / 4; splitb_kernel<<<(n4 + 255) / 256, 256>>>(in_proj_w, p_whi + OFF_IN,  p_wlo + OFF_IN,  n4);
        n4 = W_OUT_SZ / 4; splitb_kernel<<<(n4 + 255) / 256, 256>>>(out_w,     p_whi + OFF_OUT, p_wlo + OFF_OUT, n4);
        n4 = W_L1_SZ  / 4; splitb_kernel<<<(n4 + 255) / 256, 256>>>(lin1_w,    p_whi + OFF_L1,  p_wlo + OFF_L1,  n4);
        n4 = W_L2_SZ  / 4; splitb_kernel<<<(n4 + 255) / 256, 256>>>(lin2_w,    p_whi + OFF_L2,  p_wlo + OFF_L2,  n4);
    }

    for (int l = 0; l < NLAYER; l++) {
        const __nv_bfloat16* whi_in = p_whi + OFF_IN  + (size_t)l * 3 * DV * DV;
        const __nv_bfloat16* wlo_in = p_wlo + OFF_IN  + (size_t)l * 3 * DV * DV;
        const __nv_bfloat16* whi_o  = p_whi + OFF_OUT + (size_t)l * DV * DV;
        const __nv_bfloat16* wlo_o  = p_wlo + OFF_OUT + (size_t)l * DV * DV;
        const __nv_bfloat16* whi_1  = p_whi + OFF_L1  + (size_t)l * DFF * DV;
        const __nv_bfloat16* wlo_1  = p_wlo + OFF_L1  + (size_t)l * DFF * DV;
        const __nv_bfloat16* whi_2  = p_whi + OFF_L2  + (size_t)l * DV * DFF;
        const __nv_bfloat16* wlo_2  = p_wlo + OFF_L2  + (size_t)l * DV * DFF;
        const float* bq  = in_proj_b + (size_t)l * 3 * DV;
        const float* bo  = out_b     + (size_t)l * DV;
        const float* b1  = lin1_b    + (size_t)l * DFF;
        const float* b2  = lin2_b    + (size_t)l * DV;

        // QKV projection -> bf16 hi/lo qkv
        hmma_gemm<false,true><<<dim3(3 * DV / 128, MM / 128), 256, GSM_TOTAL>>>(
            p_ahi, p_alo, whi_in, wlo_in, bq, nullptr, p_qkvh, p_qkvl, 3 * DV, DV);
        // mma flash attention -> attn activation as hi/lo bf16
        attn_mma<<<dim3(BB * NH, LL / 128), 256, ASM_TOTAL>>>(
            p_qkvh, p_qkvl, dist_emb, p_kpm, p_ahi, p_alo);
        // output projection
        hmma_gemm<false,false><<<dim3(DV / 128, MM / 128), 256, GSM_TOTAL>>>(
            p_ahi, p_alo, whi_o, wlo_o, bo, p_tmp, nullptr, nullptr, DV, DV);
        // residual + LN1 -> fp32 + hi/lo
        ln_kernel<<<MM, 128>>>(p_out, p_tmp, ln1_g + (size_t)l * DV, ln1_bp + (size_t)l * DV,
                               p_out, p_ahi, p_alo);
        // FFN up: gelu epilogue writes hi/lo directly
        hmma_gemm<true,true><<<dim3(DFF / 128, MM / 128), 256, GSM_TOTAL>>>(
            p_ahi, p_alo, whi_1, wlo_1, b1, nullptr, p_hhi, p_hlo, DFF, DV);
        // FFN down
        hmma_gemm<false,false><<<dim3(DV / 128, MM / 128), 256, GSM_TOTAL>>>(
            p_hhi, p_hlo, whi_2, wlo_2, b2, p_tmp, nullptr, nullptr, DV, DFF);
        // residual + LN2 -> fp32 + hi/lo (next layer's GEMM input)
        ln_kernel<<<MM, 128>>>(p_out, p_tmp, ln2_g + (size_t)l * DV, ln2_bp + (size_t)l * DV,
                               p_out, p_ahi, p_alo);
    }

    ln_kernel<<<MM, 128>>>(p_out, (const float*)nullptr, lnf_g, lnf_bp, (float*)d_out,
                           nullptr, nullptr);
}

// round 14
// speedup vs baseline: 1.0372x; 1.0372x over previous
#include <cuda_runtime.h>
#include <cuda_bf16.h>
#include <math.h>
#include <cstdint>

#define NLAYER 6
#define DV     512
#define NH     8
#define HD     64
#define DFF    2048
#define BB     8
#define LL     1024
#define MM     (BB*LL)
#define QKV_STRIDE (3*DV)

// ---------------- scratch ----------------
__device__ float g_out [MM*DV];
__device__ float g_tmp [MM*DV];
__device__ unsigned char g_kpm[MM];

#define W_IN_SZ   (NLAYER*3*DV*DV)
#define W_OUT_SZ  (NLAYER*DV*DV)
#define W_L1_SZ   (NLAYER*DFF*DV)
#define W_L2_SZ   (NLAYER*DV*DFF)
#define W_TOT     (W_IN_SZ+W_OUT_SZ+W_L1_SZ+W_L2_SZ)
#define OFF_IN    0
#define OFF_OUT   (W_IN_SZ)
#define OFF_L1    (W_IN_SZ+W_OUT_SZ)
#define OFF_L2    (W_IN_SZ+W_OUT_SZ+W_L1_SZ)
__device__ __nv_bfloat16 g_whib[W_TOT];
__device__ __nv_bfloat16 g_wlob[W_TOT];
__device__ __nv_bfloat16 g_ahib[MM*DFF];
__device__ __nv_bfloat16 g_alob[MM*DFF];
__device__ __nv_bfloat16 g_hhib[MM*DFF];
__device__ __nv_bfloat16 g_hlob[MM*DFF];
__device__ __nv_bfloat16 g_qkvh[MM*3*DV];
__device__ __nv_bfloat16 g_qkvl[MM*3*DV];

// ---------------- smem / mma helpers ----------------
__device__ __forceinline__ uint32_t s2u(const void* p) {
    uint32_t a;
    asm("{ .reg .u64 t; cvta.to.shared.u64 t, %1; cvt.u32.u64 %0, t; }" : "=r"(a) : "l"(p));
    return a;
}
__device__ __forceinline__ void cpa16(uint32_t dst, const void* src) {
    asm volatile("cp.async.cg.shared.global [%0], [%1], 16;" :: "r"(dst), "l"(src) : "memory");
}
__device__ __forceinline__ void cpa_commit() { asm volatile("cp.async.commit_group;" ::: "memory"); }
__device__ __forceinline__ void cpa_wait0() { asm volatile("cp.async.wait_group 0;" ::: "memory"); }
__device__ __forceinline__ void cpa_wait1() { asm volatile("cp.async.wait_group 1;" ::: "memory"); }
__device__ __forceinline__ void ldmx4(uint32_t* r, uint32_t addr) {
    asm volatile("ldmatrix.sync.aligned.m8n8.x4.shared.b16 {%0,%1,%2,%3}, [%4];"
        : "=r"(r[0]), "=r"(r[1]), "=r"(r[2]), "=r"(r[3]) : "r"(addr));
}
__device__ __forceinline__ void ldmx4t(uint32_t* r, uint32_t addr) {
    asm volatile("ldmatrix.sync.aligned.m8n8.x4.trans.shared.b16 {%0,%1,%2,%3}, [%4];"
        : "=r"(r[0]), "=r"(r[1]), "=r"(r[2]), "=r"(r[3]) : "r"(addr));
}
__device__ __forceinline__ void mma_bf16(float* d, const uint32_t* a, const uint32_t* b) {
    asm volatile("mma.sync.aligned.m16n8k16.row.col.f32.bf16.bf16.f32 "
        "{%0,%1,%2,%3}, {%4,%5,%6,%7}, {%8,%9}, {%0,%1,%2,%3};"
        : "+f"(d[0]), "+f"(d[1]), "+f"(d[2]), "+f"(d[3])
        : "r"(a[0]), "r"(a[1]), "r"(a[2]), "r"(a[3]), "r"(b[0]), "r"(b[1]));
}
__device__ __forceinline__ float ex2f(float x) {
    float r;
    asm("ex2.approx.f32 %0, %1;" : "=f"(r) : "f"(x));
    return r;
}

// hi/lo bf16x2 pair from two floats (x0 -> low half)
#define CVTPAIR(dsthi, dstlo, x0, x1) do { \
    uint32_t _hp; asm("cvt.rn.bf16x2.f32 %0, %1, %2;" : "=r"(_hp) : "f"(x1), "f"(x0)); \
    float _h0 = __uint_as_float(_hp << 16); \
    float _h1 = __uint_as_float(_hp & 0xFFFF0000u); \
    uint32_t _lp; asm("cvt.rn.bf16x2.f32 %0, %1, %2;" : "=r"(_lp) : "f"((x1) - _h1), "f"((x0) - _h0)); \
    (dsthi) = _hp; (dstlo) = _lp; } while(0)

// ---------------- key padding mask ----------------
__global__ void kpm_kernel(const float* __restrict__ x, unsigned char* __restrict__ kpm)
{
    int row = blockIdx.x;
    int t = threadIdx.x;
    int nz = 0;
    for (int c = t; c < DV; c += 128)
        nz |= (x[(size_t)row * DV + c] != 0.0f) ? 1 : 0;
    nz = __syncthreads_or(nz);
    if (t == 0) kpm[row] = nz ? 0 : 1;
}

// ---------------- copy + hi/lo split (initial x) ----------------
__global__ void copy_split_kernel(const float* __restrict__ src, float* __restrict__ dst,
                                  __nv_bfloat16* __restrict__ hi, __nv_bfloat16* __restrict__ lo, int n4)
{
    int i = blockIdx.x * blockDim.x + threadIdx.x;
    if (i >= n4) return;
    float4 v = ((const float4*)src)[i];
    ((float4*)dst)[i] = v;
    __nv_bfloat16 h0 = __float2bfloat16_rn(v.x), h1 = __float2bfloat16_rn(v.y);
    __nv_bfloat16 h2 = __float2bfloat16_rn(v.z), h3 = __float2bfloat16_rn(v.w);
    __nv_bfloat162* hp = (__nv_bfloat162*)hi;
    __nv_bfloat162* lp = (__nv_bfloat162*)lo;
    hp[2*i]   = __nv_bfloat162(h0, h1);
    hp[2*i+1] = __nv_bfloat162(h2, h3);
    lp[2*i]   = __nv_bfloat162(__float2bfloat16_rn(v.x - __bfloat162float(h0)),
                               __float2bfloat16_rn(v.y - __bfloat162float(h1)));
    lp[2*i+1] = __nv_bfloat162(__float2bfloat16_rn(v.z - __bfloat162float(h2)),
                               __float2bfloat16_rn(v.w - __bfloat162float(h3)));
}

// ---------------- weight hi/lo split ----------------
__global__ void splitb_kernel(const float* __restrict__ src,
                              __nv_bfloat16* __restrict__ hi,
                              __nv_bfloat16* __restrict__ lo, int n4)
{
    int i = blockIdx.x * blockDim.x + threadIdx.x;
    if (i >= n4) return;
    float4 v = ((const float4*)src)[i];
    __nv_bfloat16 h0 = __float2bfloat16_rn(v.x), h1 = __float2bfloat16_rn(v.y);
    __nv_bfloat16 h2 = __float2bfloat16_rn(v.z), h3 = __float2bfloat16_rn(v.w);
    __nv_bfloat162* hp = (__nv_bfloat162*)hi;
    __nv_bfloat162* lp = (__nv_bfloat162*)lo;
    hp[2*i]   = __nv_bfloat162(h0, h1);
    hp[2*i+1] = __nv_bfloat162(h2, h3);
    lp[2*i]   = __nv_bfloat162(__float2bfloat16_rn(v.x - __bfloat162float(h0)),
                               __float2bfloat16_rn(v.y - __bfloat162float(h1)));
    lp[2*i+1] = __nv_bfloat162(__float2bfloat16_rn(v.z - __bfloat162float(h2)),
                               __float2bfloat16_rn(v.w - __bfloat162float(h3)));
}

// ---------------- HMMA bf16 hi/lo GEMM (3-stage cp.async, 1 barrier/chunk) ----------------
#define GSM_STAGE 32768
#define GSM_TOTAL (3*GSM_STAGE)

__device__ __forceinline__ uint32_t swz(int row, int kch) {
    return (uint32_t)(row * 64 + (((kch + ((row >> 1) & 3)) & 3) << 4));
}

template<bool GELU, bool SPLIT>
__global__ __launch_bounds__(256) void hmma_gemm(
    const __nv_bfloat16* __restrict__ Ahi, const __nv_bfloat16* __restrict__ Alo,
    const __nv_bfloat16* __restrict__ Whi, const __nv_bfloat16* __restrict__ Wlo,
    const float* __restrict__ bias, float* __restrict__ C,
    __nv_bfloat16* __restrict__ Chi, __nv_bfloat16* __restrict__ Clo,
    int N, int K)
{
    extern __shared__ __align__(16) char sm[];
    const uint32_t sb = s2u(sm);
    const int t = threadIdx.x;
    const int bm = blockIdx.y * 128, bn = blockIdx.x * 128;
    const int w = t >> 5, l = t & 31;
    const int wm = w & 3, wn = w >> 2;

    float acc[2][8][4];
#pragma unroll
    for (int mt = 0; mt < 2; mt++)
#pragma unroll
        for (int nt = 0; nt < 8; nt++)
#pragma unroll
            for (int e = 0; e < 4; e++) acc[mt][nt][e] = 0.0f;

    const int nch = K >> 5;

    auto load_stage = [&](int stage, int kt) {
        const uint32_t base = sb + stage * GSM_STAGE;
        const int k0 = kt << 5;
#pragma unroll
        for (int q = 0; q < 2; q++) {
            int ch = t + (q << 8);
            int row = ch >> 2, c = ch & 3;
            uint32_t so = swz(row, c);
            size_t ga = (size_t)(bm + row) * K + k0 + c * 8;
            size_t gb = (size_t)(bn + row) * K + k0 + c * 8;
            cpa16(base + so,          Ahi + ga);
            cpa16(base + 8192 + so,   Alo + ga);
            cpa16(base + 16384 + so,  Whi + gb);
            cpa16(base + 24576 + so,  Wlo + gb);
        }
        cpa_commit();
    };

    load_stage(0, 0);
    load_stage(1, 1);

    int stg = 0;
    for (int c = 0; c < nch; ++c) {
        if (c + 1 < nch) cpa_wait1(); else cpa_wait0();
        __syncthreads();
        if (c + 2 < nch) {
            int ns = stg + 2; if (ns >= 3) ns -= 3;
            load_stage(ns, c + 2);
        }

        const uint32_t base = sb + stg * GSM_STAGE;
#pragma unroll
        for (int kk = 0; kk < 2; kk++) {
            uint32_t ah[2][4], al[2][4];
#pragma unroll
            for (int mt = 0; mt < 2; mt++) {
                int row = wm * 32 + mt * 16 + (l & 15);
                int kch = kk * 2 + (l >> 4);
                uint32_t off = swz(row, kch);
                ldmx4(ah[mt], base + off);
                ldmx4(al[mt], base + 8192 + off);
            }
            uint32_t bh[8][2], bl[8][2];
#pragma unroll
            for (int nt2 = 0; nt2 < 4; nt2++) {
                int row = wn * 64 + nt2 * 16 + (l & 7) + ((l >> 4) << 3);
                int kch = kk * 2 + ((l >> 3) & 1);
                uint32_t off = swz(row, kch);
                uint32_t r[4];
                ldmx4(r, base + 16384 + off);
                bh[nt2*2][0] = r[0]; bh[nt2*2][1] = r[1];
                bh[nt2*2+1][0] = r[2]; bh[nt2*2+1][1] = r[3];
                ldmx4(r, base + 24576 + off);
                bl[nt2*2][0] = r[0]; bl[nt2*2][1] = r[1];
                bl[nt2*2+1][0] = r[2]; bl[nt2*2+1][1] = r[3];
            }
#pragma unroll
            for (int mt = 0; mt < 2; mt++)
#pragma unroll
                for (int nt = 0; nt < 8; nt++) {
                    mma_bf16(acc[mt][nt], ah[mt], bh[nt]);
                    mma_bf16(acc[mt][nt], ah[mt], bl[nt]);
                    mma_bf16(acc[mt][nt], al[mt], bh[nt]);
                }
        }
        if (++stg >= 3) stg = 0;
    }

#pragma unroll
    for (int mt = 0; mt < 2; mt++) {
        int row = bm + wm * 32 + mt * 16 + (l >> 2);
#pragma unroll
        for (int nt = 0; nt < 8; nt++) {
            int col = bn + wn * 64 + nt * 8 + 2 * (l & 3);
            float b0 = bias[col], b1 = bias[col + 1];
            float v0 = acc[mt][nt][0] + b0;
            float v1 = acc[mt][nt][1] + b1;
            float v2 = acc[mt][nt][2] + b0;
            float v3 = acc[mt][nt][3] + b1;
            if (GELU) {
                v0 = 0.5f * v0 * (1.0f + erff(v0 * 0.70710678118654752f));
                v1 = 0.5f * v1 * (1.0f + erff(v1 * 0.70710678118654752f));
                v2 = 0.5f * v2 * (1.0f + erff(v2 * 0.70710678118654752f));
                v3 = 0.5f * v3 * (1.0f + erff(v3 * 0.70710678118654752f));
            }
            if (SPLIT) {
                uint32_t hp, lp;
                CVTPAIR(hp, lp, v0, v1);
                *(uint32_t*)(Chi + (size_t)row * N + col) = hp;
                *(uint32_t*)(Clo + (size_t)row * N + col) = lp;
                CVTPAIR(hp, lp, v2, v3);
                *(uint32_t*)(Chi + (size_t)(row + 8) * N + col) = hp;
                *(uint32_t*)(Clo + (size_t)(row + 8) * N + col) = lp;
            } else {
                *(float2*)(C + (size_t)row * N + col)       = make_float2(v0, v1);
                *(float2*)(C + (size_t)(row + 8) * N + col) = make_float2(v2, v3);
            }
        }
    }
}

// ---------------- mma.sync flash attention ----------------
// 2-term precision: Q and P double-bf16 (hi+lo), K and V single-bf16.
// S = (qh+ql)*kh, O += (ph+pl)*vh. 128 MMAs/tile vs 192; K/V smem+traffic halved.
// smem: stages 0/1/2 at 0/16384/32768 (each: Kh @0, Vh @8192);
// sbias(log2e) @49152 (4KB), smask @53248 (4KB). Q staged in [0,32768) first.
#define ASM_TOTAL 57344

__global__ __launch_bounds__(256, 1) void attn_mma(
    const __nv_bfloat16* __restrict__ qkvh, const __nv_bfloat16* __restrict__ qkvl,
    const float* __restrict__ dist_emb, const unsigned char* __restrict__ kpm,
    __nv_bfloat16* __restrict__ ohi, __nv_bfloat16* __restrict__ olo)
{
    extern __shared__ __align__(16) char sm[];
    const uint32_t sb0 = s2u(sm);
    const int bh = blockIdx.x;
    const int b = bh >> 3, h = bh & 7;
    const int qbi = (int)gridDim.y - 1 - (int)blockIdx.y;   // long blocks first
    const int qbase = qbi * 128;
    const int t = threadIdx.x;
    const int w = t >> 5, l = t & 31;

    const float LOG2E = 1.4426950408889634f;
    float* sbias = (float*)(sm + 49152);
    float* smask = (float*)(sm + 53248);
    for (int d = t; d < LL; d += 256) {
        sbias[d] = dist_emb[d * NH + h] * LOG2E;
        smask[d] = kpm[b * LL + d] ? -2e30f : 0.0f;
    }

    // stage Q (hi @ 0, lo @ 16384) — occupies stage0+stage1 regions temporarily
#pragma unroll
    for (int q = 0; q < 4; q++) {
        int c = t + q * 256;
        int row = c >> 3, ch = c & 7;
        size_t g = (size_t)(b * LL + qbase + row) * QKV_STRIDE + h * HD + ch * 8;
        uint32_t off = (uint32_t)(row * 128 + ((ch ^ (row & 7)) << 4));
        cpa16(sb0 + off, qkvh + g);
        cpa16(sb0 + 16384 + off, qkvl + g);
    }
    cpa_commit();
    cpa_wait0();
    __syncthreads();

    uint32_t qh[4][4], ql[4][4];
    {
        int qrow = w * 16 + (l & 15);
#pragma unroll
        for (int j = 0; j < 4; j++) {
            int ch = 2 * j + (l >> 4);
            uint32_t addr = sb0 + qrow * 128 + ((ch ^ (qrow & 7)) << 4);
            ldmx4(qh[j], addr);
            ldmx4(ql[j], addr + 16384);
        }
    }
    __syncthreads();   // Q extracted before K/V overwrite

    float o[8][4];
#pragma unroll
    for (int dt = 0; dt < 8; dt++)
#pragma unroll
        for (int e = 0; e < 4; e++) o[dt][e] = 0.0f;
    float ls0 = 0.0f, ls1 = 0.0f;
    const int i0 = qbase + w * 16 + (l >> 2);
    const int i1 = i0 + 8;
    const int ntile = (qbase + 128) >> 6;

    auto load_kv = [&](int stage, int jt) {
        const uint32_t base = sb0 + stage * 16384;
#pragma unroll
        for (int q = 0; q < 2; q++) {
            int c = t + q * 256;
            int row = c >> 3, ch = c & 7;
            size_t gk = (size_t)(b * LL + jt + row) * QKV_STRIDE + DV + h * HD + ch * 8;
            size_t gv = gk + DV;
            uint32_t off = (uint32_t)(row * 128 + ((ch ^ (row & 7)) << 4));
            cpa16(base + off,        qkvh + gk);
            cpa16(base + 8192 + off, qkvh + gv);
        }
        cpa_commit();
    };

    load_kv(0, 0);
    if (ntile > 1) load_kv(1, 64);

    int stg = 0;
    for (int ti = 0; ti < ntile; ti++) {
        if (ti + 1 < ntile) cpa_wait1(); else cpa_wait0();
        __syncthreads();
        if (ti + 2 < ntile) {
            int ns = stg + 2; if (ns >= 3) ns -= 3;
            load_kv(ns, (ti + 2) << 6);
        }

        const int jt = ti << 6;
        if (jt <= qbase + w * 16 + 15) {
            const uint32_t kb = sb0 + stg * 16384;

            // ---- S = (Qh + Ql) Kh^T ----
            float s[8][4];
#pragma unroll
            for (int nt = 0; nt < 8; nt++)
#pragma unroll
                for (int e = 0; e < 4; e++) s[nt][e] = 0.0f;

            const int krow = (l & 7) + ((l >> 4) << 3);
#pragma unroll
            for (int kc = 0; kc < 4; kc++) {
                const int kch = 2 * kc + ((l >> 3) & 1);
#pragma unroll
                for (int nt2 = 0; nt2 < 4; nt2++) {
                    int row = nt2 * 16 + krow;
                    uint32_t addr = kb + row * 128 + ((kch ^ (row & 7)) << 4);
                    uint32_t rh[4];
                    ldmx4(rh, addr);
                    uint32_t b0h[2] = {rh[0], rh[1]}, b1h[2] = {rh[2], rh[3]};
                    mma_bf16(s[nt2*2],   qh[kc], b0h);
                    mma_bf16(s[nt2*2],   ql[kc], b0h);
                    mma_bf16(s[nt2*2+1], qh[kc], b1h);
                    mma_bf16(s[nt2*2+1], ql[kc], b1h);
                }
            }

            // ---- scale(log2) + bias + causal/kpm mask, direct exp2 ----
            const float scale2 = 0.125f * LOG2E;
            const int jc = jt + 2 * (l & 3);
#pragma unroll
            for (int nt = 0; nt < 8; nt++) {
                int j0 = jc + nt * 8;
                float mk0 = smask[j0], mk1 = smask[j0 + 1];
                int d0 = i0 - j0;
                int d1 = i1 - j0;
                s[nt][0] = (d0 >= 0) ? ex2f(fmaf(s[nt][0], scale2, sbias[d0]     + mk0)) : 0.0f;
                s[nt][1] = (d0 >= 1) ? ex2f(fmaf(s[nt][1], scale2, sbias[d0 - 1] + mk1)) : 0.0f;
                s[nt][2] = (d1 >= 0) ? ex2f(fmaf(s[nt][2], scale2, sbias[d1]     + mk0)) : 0.0f;
                s[nt][3] = (d1 >= 1) ? ex2f(fmaf(s[nt][3], scale2, sbias[d1 - 1] + mk1)) : 0.0f;
                ls0 += s[nt][0] + s[nt][1];
                ls1 += s[nt][2] + s[nt][3];
            }

            // ---- P -> bf16 hi/lo A-fragments ----
            uint32_t ph[4][4], pl[4][4];
#pragma unroll
            for (int j = 0; j < 4; j++) {
                CVTPAIR(ph[j][0], pl[j][0], s[2*j][0],   s[2*j][1]);
                CVTPAIR(ph[j][1], pl[j][1], s[2*j][2],   s[2*j][3]);
                CVTPAIR(ph[j][2], pl[j][2], s[2*j+1][0], s[2*j+1][1]);
                CVTPAIR(ph[j][3], pl[j][3], s[2*j+1][2], s[2*j+1][3]);
            }

            // ---- O += (Ph + Pl) Vh ----
            const int vsub = (l & 7) + (((l >> 3) & 1) << 3);
#pragma unroll
            for (int j = 0; j < 4; j++) {
                int vrow = j * 16 + vsub;
#pragma unroll
                for (int dp = 0; dp < 4; dp++) {
                    int ch = 2 * dp + (l >> 4);
                    uint32_t addr = kb + 8192 + vrow * 128 + ((ch ^ (vrow & 7)) << 4);
                    uint32_t rh[4];
                    ldmx4t(rh, addr);
                    uint32_t v0h[2] = {rh[0], rh[1]}, v1h[2] = {rh[2], rh[3]};
                    mma_bf16(o[2*dp],   ph[j], v0h);
                    mma_bf16(o[2*dp],   pl[j], v0h);
                    mma_bf16(o[2*dp+1], ph[j], v1h);
                    mma_bf16(o[2*dp+1], pl[j], v1h);
                }
            }
        }
        if (++stg >= 3) stg = 0;
    }

    // ---- finalize ----
    ls0 += __shfl_xor_sync(0xFFFFFFFFu, ls0, 1);
    ls0 += __shfl_xor_sync(0xFFFFFFFFu, ls0, 2);
    ls1 += __shfl_xor_sync(0xFFFFFFFFu, ls1, 1);
    ls1 += __shfl_xor_sync(0xFFFFFFFFu, ls1, 2);
    float inv0 = 1.0f / ls0, inv1 = 1.0f / ls1;

#pragma unroll
    for (int dt = 0; dt < 8; dt++) {
        int col = h * HD + dt * 8 + 2 * (l & 3);
        size_t r0 = (size_t)(b * LL + i0) * DV + col;
        size_t r1 = (size_t)(b * LL + i1) * DV + col;
        uint32_t hp, lp;
        CVTPAIR(hp, lp, o[dt][0] * inv0, o[dt][1] * inv0);
        *(uint32_t*)(ohi + r0) = hp;
        *(uint32_t*)(olo + r0) = lp;
        CVTPAIR(hp, lp, o[dt][2] * inv1, o[dt][3] * inv1);
        *(uint32_t*)(ohi + r1) = hp;
        *(uint32_t*)(olo + r1) = lp;
    }
}

// ---------------- residual + LayerNorm (float4, optional bf16 hi/lo out) ----------------
__global__ __launch_bounds__(128) void ln_kernel(
    const float* __restrict__ x, const float* __restrict__ res,
    const float* __restrict__ g, const float* __restrict__ beta,
    float* __restrict__ outp,
    __nv_bfloat16* __restrict__ ohi, __nv_bfloat16* __restrict__ olo)
{
    const int row = blockIdx.x;
    const int t = threadIdx.x;
    const size_t base = (size_t)row * DV + 4 * t;

    float4 v = *(const float4*)(x + base);
    if (res) {
        float4 rv = *(const float4*)(res + base);
        v.x += rv.x; v.y += rv.y; v.z += rv.z; v.w += rv.w;
    }
    float s  = v.x + v.y + v.z + v.w;
    float ss = v.x * v.x + v.y * v.y + v.z * v.z + v.w * v.w;
#pragma unroll
    for (int o = 16; o > 0; o >>= 1) {
        s  += __shfl_xor_sync(0xFFFFFFFFu, s,  o);
        ss += __shfl_xor_sync(0xFFFFFFFFu, ss, o);
    }
    __shared__ float rs[4], rss[4];
    int w = t >> 5;
    if ((t & 31) == 0) { rs[w] = s; rss[w] = ss; }
    __syncthreads();
    s  = rs[0] + rs[1] + rs[2] + rs[3];
    ss = rss[0] + rss[1] + rss[2] + rss[3];
    float mean = s * (1.0f / DV);
    float var  = ss * (1.0f / DV) - mean * mean;
    float r = rsqrtf(var + 1e-5f);

    float4 gv = *(const float4*)(g + 4 * t);
    float4 bv = *(const float4*)(beta + 4 * t);
    float4 ov;
    ov.x = (v.x - mean) * r * gv.x + bv.x;
    ov.y = (v.y - mean) * r * gv.y + bv.y;
    ov.z = (v.z - mean) * r * gv.z + bv.z;
    ov.w = (v.w - mean) * r * gv.w + bv.w;
    *(float4*)(outp + base) = ov;
    if (ohi) {
        uint32_t hp, lp;
        CVTPAIR(hp, lp, ov.x, ov.y);
        *(uint32_t*)(ohi + base) = hp;
        *(uint32_t*)(olo + base) = lp;
        CVTPAIR(hp, lp, ov.z, ov.w);
        *(uint32_t*)(ohi + base + 2) = hp;
        *(uint32_t*)(olo + base + 2) = lp;
    }
}

// ---------------- host launcher ----------------
extern "C" void kernel_launch(void* const* d_in, const int* in_sizes, int n_in,
                              void* d_out, int out_size)
{
    (void)in_sizes; (void)n_in; (void)out_size;
    const float* x         = (const float*)d_in[0];
    const float* dist_emb  = (const float*)d_in[1];
    const float* in_proj_w = (const float*)d_in[2];
    const float* in_proj_b = (const float*)d_in[3];
    const float* out_w     = (const float*)d_in[4];
    const float* out_b     = (const float*)d_in[5];
    const float* lin1_w    = (const float*)d_in[6];
    const float* lin1_b    = (const float*)d_in[7];
    const float* lin2_w    = (const float*)d_in[8];
    const float* lin2_b    = (const float*)d_in[9];
    const float* ln1_g     = (const float*)d_in[10];
    const float* ln1_bp    = (const float*)d_in[11];
    const float* ln2_g     = (const float*)d_in[12];
    const float* ln2_bp    = (const float*)d_in[13];
    const float* lnf_g     = (const float*)d_in[14];
    const float* lnf_bp    = (const float*)d_in[15];

    float *p_out, *p_tmp;
    __nv_bfloat16 *p_whi, *p_wlo, *p_ahi, *p_alo, *p_hhi, *p_hlo, *p_qkvh, *p_qkvl;
    unsigned char* p_kpm;
    cudaGetSymbolAddress((void**)&p_out,  g_out);
    cudaGetSymbolAddress((void**)&p_tmp,  g_tmp);
    cudaGetSymbolAddress((void**)&p_whi,  g_whib);
    cudaGetSymbolAddress((void**)&p_wlo,  g_wlob);
    cudaGetSymbolAddress((void**)&p_ahi,  g_ahib);
    cudaGetSymbolAddress((void**)&p_alo,  g_alob);
    cudaGetSymbolAddress((void**)&p_hhi,  g_hhib);
    cudaGetSymbolAddress((void**)&p_hlo,  g_hlob);
    cudaGetSymbolAddress((void**)&p_qkvh, g_qkvh);
    cudaGetSymbolAddress((void**)&p_qkvl, g_qkvl);
    cudaGetSymbolAddress((void**)&p_kpm,  g_kpm);

    cudaFuncSetAttribute(hmma_gemm<false,false>, cudaFuncAttributeMaxDynamicSharedMemorySize, GSM_TOTAL);
    cudaFuncSetAttribute(hmma_gemm<false,true>,  cudaFuncAttributeMaxDynamicSharedMemorySize, GSM_TOTAL);
    cudaFuncSetAttribute(hmma_gemm<true,true>,   cudaFuncAttributeMaxDynamicSharedMemorySize, GSM_TOTAL);
    cudaFuncSetAttribute(attn_mma, cudaFuncAttributeMaxDynamicSharedMemorySize, ASM_TOTAL);

    kpm_kernel<<<MM, 128>>>(x, p_kpm);
    {
        int n4 = MM * DV / 4;
        copy_split_kernel<<<(n4 + 255) / 256, 256>>>(x, p_out, p_ahi, p_alo, n4);
    }

    // split weights once
    {
        int n4;
        n4 = W_IN_SZ  / 4; splitb_kernel<<<(n4 + 255) / 256, 256>>>(in_proj_w, p_whi + OFF_IN,  p_wlo + OFF_IN,  n4);
        n4 = W_OUT_SZ / 4; splitb_kernel<<<(n4 + 255) / 256, 256>>>(out_w,     p_whi + OFF_OUT, p_wlo + OFF_OUT, n4);
        n4 = W_L1_SZ  / 4; splitb_kernel<<<(n4 + 255) / 256, 256>>>(lin1_w,    p_whi + OFF_L1,  p_wlo + OFF_L1,  n4);
        n4 = W_L2_SZ  / 4; splitb_kernel<<<(n4 + 255) / 256, 256>>>(lin2_w,    p_whi + OFF_L2,  p_wlo + OFF_L2,  n4);
    }

    for (int l = 0; l < NLAYER; l++) {
        const __nv_bfloat16* whi_in = p_whi + OFF_IN  + (size_t)l * 3 * DV * DV;
        const __nv_bfloat16* wlo_in = p_wlo + OFF_IN  + (size_t)l * 3 * DV * DV;
        const __nv_bfloat16* whi_o  = p_whi + OFF_OUT + (size_t)l * DV * DV;
        const __nv_bfloat16* wlo_o  = p_wlo + OFF_OUT + (size_t)l * DV * DV;
        const __nv_bfloat16* whi_1  = p_whi + OFF_L1  + (size_t)l * DFF * DV;
        const __nv_bfloat16* wlo_1  = p_wlo + OFF_L1  + (size_t)l * DFF * DV;
        const __nv_bfloat16* whi_2  = p_whi + OFF_L2  + (size_t)l * DV * DFF;
        const __nv_bfloat16* wlo_2  = p_wlo + OFF_L2  + (size_t)l * DV * DFF;
        const float* bq  = in_proj_b + (size_t)l * 3 * DV;
        const float* bo  = out_b     + (size_t)l * DV;
        const float* b1  = lin1_b    + (size_t)l * DFF;
        const float* b2  = lin2_b    + (size_t)l * DV;

        // QKV projection -> bf16 hi/lo qkv
        hmma_gemm<false,true><<<dim3(3 * DV / 128, MM / 128), 256, GSM_TOTAL>>>(
            p_ahi, p_alo, whi_in, wlo_in, bq, nullptr, p_qkvh, p_qkvl, 3 * DV, DV);
        // mma flash attention -> attn activation as hi/lo bf16
        attn_mma<<<dim3(BB * NH, LL / 128), 256, ASM_TOTAL>>>(
            p_qkvh, p_qkvl, dist_emb, p_kpm, p_ahi, p_alo);
        // output projection
        hmma_gemm<false,false><<<dim3(DV / 128, MM / 128), 256, GSM_TOTAL>>>(
            p_ahi, p_alo, whi_o, wlo_o, bo, p_tmp, nullptr, nullptr, DV, DV);
        // residual + LN1 -> fp32 + hi/lo
        ln_kernel<<<MM, 128>>>(p_out, p_tmp, ln1_g + (size_t)l * DV, ln1_bp + (size_t)l * DV,
                               p_out, p_ahi, p_alo);
        // FFN up: gelu epilogue writes hi/lo directly
        hmma_gemm<true,true><<<dim3(DFF / 128, MM / 128), 256, GSM_TOTAL>>>(
            p_ahi, p_alo, whi_1, wlo_1, b1, nullptr, p_hhi, p_hlo, DFF, DV);
        // FFN down
        hmma_gemm<false,false><<<dim3(DV / 128, MM / 128), 256, GSM_TOTAL>>>(
            p_hhi, p_hlo, whi_2, wlo_2, b2, p_tmp, nullptr, nullptr, DV, DFF);
        // residual + LN2 -> fp32 + hi/lo (next layer's GEMM input)
        ln_kernel<<<MM, 128>>>(p_out, p_tmp, ln2_g + (size_t)l * DV, ln2_bp + (size_t)l * DV,
                               p_out, p_ahi, p_alo);
    }

    ln_kernel<<<MM, 128>>>(p_out, (const float*)nullptr, lnf_g, lnf_bp, (float*)d_out,
                           nullptr, nullptr);
}

// round 15
// speedup vs baseline: 1.0836x; 1.0447x over previous
#include <cuda_runtime.h>
#include <cuda_bf16.h>
#include <math.h>
#include <cstdint>

#define NLAYER 6
#define DV     512
#define NH     8
#define HD     64
#define DFF    2048
#define BB     8
#define LL     1024
#define MM     (BB*LL)
#define QKV_STRIDE (3*DV)

// ---------------- scratch ----------------
__device__ float g_out [MM*DV];
__device__ float g_tmp [MM*DV];
__device__ unsigned char g_kpm[MM];

#define W_IN_SZ   (NLAYER*3*DV*DV)
#define W_OUT_SZ  (NLAYER*DV*DV)
#define W_L1_SZ   (NLAYER*DFF*DV)
#define W_L2_SZ   (NLAYER*DV*DFF)
#define W_TOT     (W_IN_SZ+W_OUT_SZ+W_L1_SZ+W_L2_SZ)
#define OFF_IN    0
#define OFF_OUT   (W_IN_SZ)
#define OFF_L1    (W_IN_SZ+W_OUT_SZ)
#define OFF_L2    (W_IN_SZ+W_OUT_SZ+W_L1_SZ)
__device__ __nv_bfloat16 g_whib[W_TOT];
__device__ __nv_bfloat16 g_wlob[W_TOT];
__device__ __nv_bfloat16 g_ahib[MM*DFF];
__device__ __nv_bfloat16 g_alob[MM*DFF];
__device__ __nv_bfloat16 g_hhib[MM*DFF];
__device__ __nv_bfloat16 g_hlob[MM*DFF];
__device__ __nv_bfloat16 g_qkvh[MM*3*DV];

// ---------------- smem / mma helpers ----------------
__device__ __forceinline__ uint32_t s2u(const void* p) {
    uint32_t a;
    asm("{ .reg .u64 t; cvta.to.shared.u64 t, %1; cvt.u32.u64 %0, t; }" : "=r"(a) : "l"(p));
    return a;
}
__device__ __forceinline__ void cpa16(uint32_t dst, const void* src) {
    asm volatile("cp.async.cg.shared.global [%0], [%1], 16;" :: "r"(dst), "l"(src) : "memory");
}
__device__ __forceinline__ void cpa_commit() { asm volatile("cp.async.commit_group;" ::: "memory"); }
__device__ __forceinline__ void cpa_wait0() { asm volatile("cp.async.wait_group 0;" ::: "memory"); }
__device__ __forceinline__ void cpa_wait1() { asm volatile("cp.async.wait_group 1;" ::: "memory"); }
__device__ __forceinline__ void ldmx4(uint32_t* r, uint32_t addr) {
    asm volatile("ldmatrix.sync.aligned.m8n8.x4.shared.b16 {%0,%1,%2,%3}, [%4];"
        : "=r"(r[0]), "=r"(r[1]), "=r"(r[2]), "=r"(r[3]) : "r"(addr));
}
__device__ __forceinline__ void ldmx4t(uint32_t* r, uint32_t addr) {
    asm volatile("ldmatrix.sync.aligned.m8n8.x4.trans.shared.b16 {%0,%1,%2,%3}, [%4];"
        : "=r"(r[0]), "=r"(r[1]), "=r"(r[2]), "=r"(r[3]) : "r"(addr));
}
__device__ __forceinline__ void mma_bf16(float* d, const uint32_t* a, const uint32_t* b) {
    asm volatile("mma.sync.aligned.m16n8k16.row.col.f32.bf16.bf16.f32 "
        "{%0,%1,%2,%3}, {%4,%5,%6,%7}, {%8,%9}, {%0,%1,%2,%3};"
        : "+f"(d[0]), "+f"(d[1]), "+f"(d[2]), "+f"(d[3])
        : "r"(a[0]), "r"(a[1]), "r"(a[2]), "r"(a[3]), "r"(b[0]), "r"(b[1]));
}
__device__ __forceinline__ float ex2f(float x) {
    float r;
    asm("ex2.approx.f32 %0, %1;" : "=f"(r) : "f"(x));
    return r;
}
__device__ __forceinline__ uint32_t cvt1(float x0, float x1) {
    uint32_t p;
    asm("cvt.rn.bf16x2.f32 %0, %1, %2;" : "=r"(p) : "f"(x1), "f"(x0));
    return p;
}

// hi/lo bf16x2 pair from two floats (x0 -> low half)
#define CVTPAIR(dsthi, dstlo, x0, x1) do { \
    uint32_t _hp; asm("cvt.rn.bf16x2.f32 %0, %1, %2;" : "=r"(_hp) : "f"(x1), "f"(x0)); \
    float _h0 = __uint_as_float(_hp << 16); \
    float _h1 = __uint_as_float(_hp & 0xFFFF0000u); \
    uint32_t _lp; asm("cvt.rn.bf16x2.f32 %0, %1, %2;" : "=r"(_lp) : "f"((x1) - _h1), "f"((x0) - _h0)); \
    (dsthi) = _hp; (dstlo) = _lp; } while(0)

// ---------------- key padding mask ----------------
__global__ void kpm_kernel(const float* __restrict__ x, unsigned char* __restrict__ kpm)
{
    int row = blockIdx.x;
    int t = threadIdx.x;
    int nz = 0;
    for (int c = t; c < DV; c += 128)
        nz |= (x[(size_t)row * DV + c] != 0.0f) ? 1 : 0;
    nz = __syncthreads_or(nz);
    if (t == 0) kpm[row] = nz ? 0 : 1;
}

// ---------------- copy + hi/lo split (initial x) ----------------
__global__ void copy_split_kernel(const float* __restrict__ src, float* __restrict__ dst,
                                  __nv_bfloat16* __restrict__ hi, __nv_bfloat16* __restrict__ lo, int n4)
{
    int i = blockIdx.x * blockDim.x + threadIdx.x;
    if (i >= n4) return;
    float4 v = ((const float4*)src)[i];
    ((float4*)dst)[i] = v;
    __nv_bfloat16 h0 = __float2bfloat16_rn(v.x), h1 = __float2bfloat16_rn(v.y);
    __nv_bfloat16 h2 = __float2bfloat16_rn(v.z), h3 = __float2bfloat16_rn(v.w);
    __nv_bfloat162* hp = (__nv_bfloat162*)hi;
    __nv_bfloat162* lp = (__nv_bfloat162*)lo;
    hp[2*i]   = __nv_bfloat162(h0, h1);
    hp[2*i+1] = __nv_bfloat162(h2, h3);
    lp[2*i]   = __nv_bfloat162(__float2bfloat16_rn(v.x - __bfloat162float(h0)),
                               __float2bfloat16_rn(v.y - __bfloat162float(h1)));
    lp[2*i+1] = __nv_bfloat162(__float2bfloat16_rn(v.z - __bfloat162float(h2)),
                               __float2bfloat16_rn(v.w - __bfloat162float(h3)));
}

// ---------------- weight hi/lo split ----------------
__global__ void splitb_kernel(const float* __restrict__ src,
                              __nv_bfloat16* __restrict__ hi,
                              __nv_bfloat16* __restrict__ lo, int n4)
{
    int i = blockIdx.x * blockDim.x + threadIdx.x;
    if (i >= n4) return;
    float4 v = ((const float4*)src)[i];
    __nv_bfloat16 h0 = __float2bfloat16_rn(v.x), h1 = __float2bfloat16_rn(v.y);
    __nv_bfloat16 h2 = __float2bfloat16_rn(v.z), h3 = __float2bfloat16_rn(v.w);
    __nv_bfloat162* hp = (__nv_bfloat162*)hi;
    __nv_bfloat162* lp = (__nv_bfloat162*)lo;
    hp[2*i]   = __nv_bfloat162(h0, h1);
    hp[2*i+1] = __nv_bfloat162(h2, h3);
    lp[2*i]   = __nv_bfloat162(__float2bfloat16_rn(v.x - __bfloat162float(h0)),
                               __float2bfloat16_rn(v.y - __bfloat162float(h1)));
    lp[2*i+1] = __nv_bfloat162(__float2bfloat16_rn(v.z - __bfloat162float(h2)),
                               __float2bfloat16_rn(v.w - __bfloat162float(h3)));
}

// ---------------- HMMA bf16 hi/lo GEMM (3-stage cp.async, 1 barrier/chunk) ----------------
// SPLIT epilogue: writes Chi always; Clo only if non-null.
#define GSM_STAGE 32768
#define GSM_TOTAL (3*GSM_STAGE)

__device__ __forceinline__ uint32_t swz(int row, int kch) {
    return (uint32_t)(row * 64 + (((kch + ((row >> 1) & 3)) & 3) << 4));
}

template<bool GELU, bool SPLIT>
__global__ __launch_bounds__(256) void hmma_gemm(
    const __nv_bfloat16* __restrict__ Ahi, const __nv_bfloat16* __restrict__ Alo,
    const __nv_bfloat16* __restrict__ Whi, const __nv_bfloat16* __restrict__ Wlo,
    const float* __restrict__ bias, float* __restrict__ C,
    __nv_bfloat16* __restrict__ Chi, __nv_bfloat16* __restrict__ Clo,
    int N, int K)
{
    extern __shared__ __align__(16) char sm[];
    const uint32_t sb = s2u(sm);
    const int t = threadIdx.x;
    const int bm = blockIdx.y * 128, bn = blockIdx.x * 128;
    const int w = t >> 5, l = t & 31;
    const int wm = w & 3, wn = w >> 2;

    float acc[2][8][4];
#pragma unroll
    for (int mt = 0; mt < 2; mt++)
#pragma unroll
        for (int nt = 0; nt < 8; nt++)
#pragma unroll
            for (int e = 0; e < 4; e++) acc[mt][nt][e] = 0.0f;

    const int nch = K >> 5;

    auto load_stage = [&](int stage, int kt) {
        const uint32_t base = sb + stage * GSM_STAGE;
        const int k0 = kt << 5;
#pragma unroll
        for (int q = 0; q < 2; q++) {
            int ch = t + (q << 8);
            int row = ch >> 2, c = ch & 3;
            uint32_t so = swz(row, c);
            size_t ga = (size_t)(bm + row) * K + k0 + c * 8;
            size_t gb = (size_t)(bn + row) * K + k0 + c * 8;
            cpa16(base + so,          Ahi + ga);
            cpa16(base + 8192 + so,   Alo + ga);
            cpa16(base + 16384 + so,  Whi + gb);
            cpa16(base + 24576 + so,  Wlo + gb);
        }
        cpa_commit();
    };

    load_stage(0, 0);
    load_stage(1, 1);

    int stg = 0;
    for (int c = 0; c < nch; ++c) {
        if (c + 1 < nch) cpa_wait1(); else cpa_wait0();
        __syncthreads();
        if (c + 2 < nch) {
            int ns = stg + 2; if (ns >= 3) ns -= 3;
            load_stage(ns, c + 2);
        }

        const uint32_t base = sb + stg * GSM_STAGE;
#pragma unroll
        for (int kk = 0; kk < 2; kk++) {
            uint32_t ah[2][4], al[2][4];
#pragma unroll
            for (int mt = 0; mt < 2; mt++) {
                int row = wm * 32 + mt * 16 + (l & 15);
                int kch = kk * 2 + (l >> 4);
                uint32_t off = swz(row, kch);
                ldmx4(ah[mt], base + off);
                ldmx4(al[mt], base + 8192 + off);
            }
            uint32_t bh[8][2], bl[8][2];
#pragma unroll
            for (int nt2 = 0; nt2 < 4; nt2++) {
                int row = wn * 64 + nt2 * 16 + (l & 7) + ((l >> 4) << 3);
                int kch = kk * 2 + ((l >> 3) & 1);
                uint32_t off = swz(row, kch);
                uint32_t r[4];
                ldmx4(r, base + 16384 + off);
                bh[nt2*2][0] = r[0]; bh[nt2*2][1] = r[1];
                bh[nt2*2+1][0] = r[2]; bh[nt2*2+1][1] = r[3];
                ldmx4(r, base + 24576 + off);
                bl[nt2*2][0] = r[0]; bl[nt2*2][1] = r[1];
                bl[nt2*2+1][0] = r[2]; bl[nt2*2+1][1] = r[3];
            }
#pragma unroll
            for (int mt = 0; mt < 2; mt++)
#pragma unroll
                for (int nt = 0; nt < 8; nt++) {
                    mma_bf16(acc[mt][nt], ah[mt], bh[nt]);
                    mma_bf16(acc[mt][nt], ah[mt], bl[nt]);
                    mma_bf16(acc[mt][nt], al[mt], bh[nt]);
                }
        }
        if (++stg >= 3) stg = 0;
    }

#pragma unroll
    for (int mt = 0; mt < 2; mt++) {
        int row = bm + wm * 32 + mt * 16 + (l >> 2);
#pragma unroll
        for (int nt = 0; nt < 8; nt++) {
            int col = bn + wn * 64 + nt * 8 + 2 * (l & 3);
            float b0 = bias[col], b1 = bias[col + 1];
            float v0 = acc[mt][nt][0] + b0;
            float v1 = acc[mt][nt][1] + b1;
            float v2 = acc[mt][nt][2] + b0;
            float v3 = acc[mt][nt][3] + b1;
            if (GELU) {
                v0 = 0.5f * v0 * (1.0f + erff(v0 * 0.70710678118654752f));
                v1 = 0.5f * v1 * (1.0f + erff(v1 * 0.70710678118654752f));
                v2 = 0.5f * v2 * (1.0f + erff(v2 * 0.70710678118654752f));
                v3 = 0.5f * v3 * (1.0f + erff(v3 * 0.70710678118654752f));
            }
            if (SPLIT) {
                if (Clo) {
                    uint32_t hp, lp;
                    CVTPAIR(hp, lp, v0, v1);
                    *(uint32_t*)(Chi + (size_t)row * N + col) = hp;
                    *(uint32_t*)(Clo + (size_t)row * N + col) = lp;
                    CVTPAIR(hp, lp, v2, v3);
                    *(uint32_t*)(Chi + (size_t)(row + 8) * N + col) = hp;
                    *(uint32_t*)(Clo + (size_t)(row + 8) * N + col) = lp;
                } else {
                    *(uint32_t*)(Chi + (size_t)row * N + col)       = cvt1(v0, v1);
                    *(uint32_t*)(Chi + (size_t)(row + 8) * N + col) = cvt1(v2, v3);
                }
            } else {
                *(float2*)(C + (size_t)row * N + col)       = make_float2(v0, v1);
                *(float2*)(C + (size_t)(row + 8) * N + col) = make_float2(v2, v3);
            }
        }
    }
}

// ---------------- mma.sync flash attention ----------------
// Single-bf16 Q, K, V, P: S = qh*kh, O += ph*vh. 64 MMAs/tile.
// smem: stages 0/1/2 at 0/16384/32768 (each: Kh @0, Vh @8192);
// sbias(log2e) @49152 (4KB), smask @53248 (4KB). Q staged in stage0 first.
#define ASM_TOTAL 57344

__global__ __launch_bounds__(256, 1) void attn_mma(
    const __nv_bfloat16* __restrict__ qkvh,
    const float* __restrict__ dist_emb, const unsigned char* __restrict__ kpm,
    __nv_bfloat16* __restrict__ ohi, __nv_bfloat16* __restrict__ olo)
{
    extern __shared__ __align__(16) char sm[];
    const uint32_t sb0 = s2u(sm);
    const int bh = blockIdx.x;
    const int b = bh >> 3, h = bh & 7;
    const int qbi = (int)gridDim.y - 1 - (int)blockIdx.y;   // long blocks first
    const int qbase = qbi * 128;
    const int t = threadIdx.x;
    const int w = t >> 5, l = t & 31;

    const float LOG2E = 1.4426950408889634f;
    float* sbias = (float*)(sm + 49152);
    float* smask = (float*)(sm + 53248);
    for (int d = t; d < LL; d += 256) {
        sbias[d] = dist_emb[d * NH + h] * LOG2E;
        smask[d] = kpm[b * LL + d] ? -2e30f : 0.0f;
    }

    // stage Q (hi only @ 0)
#pragma unroll
    for (int q = 0; q < 4; q++) {
        int c = t + q * 256;
        int row = c >> 3, ch = c & 7;
        size_t g = (size_t)(b * LL + qbase + row) * QKV_STRIDE + h * HD + ch * 8;
        uint32_t off = (uint32_t)(row * 128 + ((ch ^ (row & 7)) << 4));
        cpa16(sb0 + off, qkvh + g);
    }
    cpa_commit();
    cpa_wait0();
    __syncthreads();

    uint32_t qh[4][4];
    {
        int qrow = w * 16 + (l & 15);
#pragma unroll
        for (int j = 0; j < 4; j++) {
            int ch = 2 * j + (l >> 4);
            uint32_t addr = sb0 + qrow * 128 + ((ch ^ (qrow & 7)) << 4);
            ldmx4(qh[j], addr);
        }
    }
    __syncthreads();   // Q extracted before K/V overwrite

    float o[8][4];
#pragma unroll
    for (int dt = 0; dt < 8; dt++)
#pragma unroll
        for (int e = 0; e < 4; e++) o[dt][e] = 0.0f;
    float ls0 = 0.0f, ls1 = 0.0f;
    const int i0 = qbase + w * 16 + (l >> 2);
    const int i1 = i0 + 8;
    const int ntile = (qbase + 128) >> 6;

    auto load_kv = [&](int stage, int jt) {
        const uint32_t base = sb0 + stage * 16384;
#pragma unroll
        for (int q = 0; q < 2; q++) {
            int c = t + q * 256;
            int row = c >> 3, ch = c & 7;
            size_t gk = (size_t)(b * LL + jt + row) * QKV_STRIDE + DV + h * HD + ch * 8;
            size_t gv = gk + DV;
            uint32_t off = (uint32_t)(row * 128 + ((ch ^ (row & 7)) << 4));
            cpa16(base + off,        qkvh + gk);
            cpa16(base + 8192 + off, qkvh + gv);
        }
        cpa_commit();
    };

    load_kv(0, 0);
    if (ntile > 1) load_kv(1, 64);

    int stg = 0;
    for (int ti = 0; ti < ntile; ti++) {
        if (ti + 1 < ntile) cpa_wait1(); else cpa_wait0();
        __syncthreads();
        if (ti + 2 < ntile) {
            int ns = stg + 2; if (ns >= 3) ns -= 3;
            load_kv(ns, (ti + 2) << 6);
        }

        const int jt = ti << 6;
        if (jt <= qbase + w * 16 + 15) {
            const uint32_t kb = sb0 + stg * 16384;

            // ---- S = Qh Kh^T ----
            float s[8][4];
#pragma unroll
            for (int nt = 0; nt < 8; nt++)
#pragma unroll
                for (int e = 0; e < 4; e++) s[nt][e] = 0.0f;

            const int krow = (l & 7) + ((l >> 4) << 3);
#pragma unroll
            for (int kc = 0; kc < 4; kc++) {
                const int kch = 2 * kc + ((l >> 3) & 1);
#pragma unroll
                for (int nt2 = 0; nt2 < 4; nt2++) {
                    int row = nt2 * 16 + krow;
                    uint32_t addr = kb + row * 128 + ((kch ^ (row & 7)) << 4);
                    uint32_t rh[4];
                    ldmx4(rh, addr);
                    uint32_t b0h[2] = {rh[0], rh[1]}, b1h[2] = {rh[2], rh[3]};
                    mma_bf16(s[nt2*2],   qh[kc], b0h);
                    mma_bf16(s[nt2*2+1], qh[kc], b1h);
                }
            }

            // ---- scale(log2) + bias + causal/kpm mask, direct exp2 ----
            const float scale2 = 0.125f * LOG2E;
            const int jc = jt + 2 * (l & 3);
#pragma unroll
            for (int nt = 0; nt < 8; nt++) {
                int j0 = jc + nt * 8;
                float mk0 = smask[j0], mk1 = smask[j0 + 1];
                int d0 = i0 - j0;
                int d1 = i1 - j0;
                s[nt][0] = (d0 >= 0) ? ex2f(fmaf(s[nt][0], scale2, sbias[d0]     + mk0)) : 0.0f;
                s[nt][1] = (d0 >= 1) ? ex2f(fmaf(s[nt][1], scale2, sbias[d0 - 1] + mk1)) : 0.0f;
                s[nt][2] = (d1 >= 0) ? ex2f(fmaf(s[nt][2], scale2, sbias[d1]     + mk0)) : 0.0f;
                s[nt][3] = (d1 >= 1) ? ex2f(fmaf(s[nt][3], scale2, sbias[d1 - 1] + mk1)) : 0.0f;
                ls0 += s[nt][0] + s[nt][1];
                ls1 += s[nt][2] + s[nt][3];
            }

            // ---- P -> single-bf16 A-fragments ----
            uint32_t ph[4][4];
#pragma unroll
            for (int j = 0; j < 4; j++) {
                ph[j][0] = cvt1(s[2*j][0],   s[2*j][1]);
                ph[j][1] = cvt1(s[2*j][2],   s[2*j][3]);
                ph[j][2] = cvt1(s[2*j+1][0], s[2*j+1][1]);
                ph[j][3] = cvt1(s[2*j+1][2], s[2*j+1][3]);
            }

            // ---- O += Ph Vh ----
            const int vsub = (l & 7) + (((l >> 3) & 1) << 3);
#pragma unroll
            for (int j = 0; j < 4; j++) {
                int vrow = j * 16 + vsub;
#pragma unroll
                for (int dp = 0; dp < 4; dp++) {
                    int ch = 2 * dp + (l >> 4);
                    uint32_t addr = kb + 8192 + vrow * 128 + ((ch ^ (vrow & 7)) << 4);
                    uint32_t rh[4];
                    ldmx4t(rh, addr);
                    uint32_t v0h[2] = {rh[0], rh[1]}, v1h[2] = {rh[2], rh[3]};
                    mma_bf16(o[2*dp],   ph[j], v0h);
                    mma_bf16(o[2*dp+1], ph[j], v1h);
                }
            }
        }
        if (++stg >= 3) stg = 0;
    }

    // ---- finalize ----
    ls0 += __shfl_xor_sync(0xFFFFFFFFu, ls0, 1);
    ls0 += __shfl_xor_sync(0xFFFFFFFFu, ls0, 2);
    ls1 += __shfl_xor_sync(0xFFFFFFFFu, ls1, 1);
    ls1 += __shfl_xor_sync(0xFFFFFFFFu, ls1, 2);
    float inv0 = 1.0f / ls0, inv1 = 1.0f / ls1;

#pragma unroll
    for (int dt = 0; dt < 8; dt++) {
        int col = h * HD + dt * 8 + 2 * (l & 3);
        size_t r0 = (size_t)(b * LL + i0) * DV + col;
        size_t r1 = (size_t)(b * LL + i1) * DV + col;
        uint32_t hp, lp;
        CVTPAIR(hp, lp, o[dt][0] * inv0, o[dt][1] * inv0);
        *(uint32_t*)(ohi + r0) = hp;
        *(uint32_t*)(olo + r0) = lp;
        CVTPAIR(hp, lp, o[dt][2] * inv1, o[dt][3] * inv1);
        *(uint32_t*)(ohi + r1) = hp;
        *(uint32_t*)(olo + r1) = lp;
    }
}

// ---------------- residual + LayerNorm (float4, optional bf16 hi/lo out) ----------------
__global__ __launch_bounds__(128) void ln_kernel(
    const float* __restrict__ x, const float* __restrict__ res,
    const float* __restrict__ g, const float* __restrict__ beta,
    float* __restrict__ outp,
    __nv_bfloat16* __restrict__ ohi, __nv_bfloat16* __restrict__ olo)
{
    const int row = blockIdx.x;
    const int t = threadIdx.x;
    const size_t base = (size_t)row * DV + 4 * t;

    float4 v = *(const float4*)(x + base);
    if (res) {
        float4 rv = *(const float4*)(res + base);
        v.x += rv.x; v.y += rv.y; v.z += rv.z; v.w += rv.w;
    }
    float s  = v.x + v.y + v.z + v.w;
    float ss = v.x * v.x + v.y * v.y + v.z * v.z + v.w * v.w;
#pragma unroll
    for (int o = 16; o > 0; o >>= 1) {
        s  += __shfl_xor_sync(0xFFFFFFFFu, s,  o);
        ss += __shfl_xor_sync(0xFFFFFFFFu, ss, o);
    }
    __shared__ float rs[4], rss[4];
    int w = t >> 5;
    if ((t & 31) == 0) { rs[w] = s; rss[w] = ss; }
    __syncthreads();
    s  = rs[0] + rs[1] + rs[2] + rs[3];
    ss = rss[0] + rss[1] + rss[2] + rss[3];
    float mean = s * (1.0f / DV);
    float var  = ss * (1.0f / DV) - mean * mean;
    float r = rsqrtf(var + 1e-5f);

    float4 gv = *(const float4*)(g + 4 * t);
    float4 bv = *(const float4*)(beta + 4 * t);
    float4 ov;
    ov.x = (v.x - mean) * r * gv.x + bv.x;
    ov.y = (v.y - mean) * r * gv.y + bv.y;
    ov.z = (v.z - mean) * r * gv.z + bv.z;
    ov.w = (v.w - mean) * r * gv.w + bv.w;
    *(float4*)(outp + base) = ov;
    if (ohi) {
        uint32_t hp, lp;
        CVTPAIR(hp, lp, ov.x, ov.y);
        *(uint32_t*)(ohi + base) = hp;
        *(uint32_t*)(olo + base) = lp;
        CVTPAIR(hp, lp, ov.z, ov.w);
        *(uint32_t*)(ohi + base + 2) = hp;
        *(uint32_t*)(olo + base + 2) = lp;
    }
}

// ---------------- host launcher ----------------
extern "C" void kernel_launch(void* const* d_in, const int* in_sizes, int n_in,
                              void* d_out, int out_size)
{
    (void)in_sizes; (void)n_in; (void)out_size;
    const float* x         = (const float*)d_in[0];
    const float* dist_emb  = (const float*)d_in[1];
    const float* in_proj_w = (const float*)d_in[2];
    const float* in_proj_b = (const float*)d_in[3];
    const float* out_w     = (const float*)d_in[4];
    const float* out_b     = (const float*)d_in[5];
    const float* lin1_w    = (const float*)d_in[6];
    const float* lin1_b    = (const float*)d_in[7];
    const float* lin2_w    = (const float*)d_in[8];
    const float* lin2_b    = (const float*)d_in[9];
    const float* ln1_g     = (const float*)d_in[10];
    const float* ln1_bp    = (const float*)d_in[11];
    const float* ln2_g     = (const float*)d_in[12];
    const float* ln2_bp    = (const float*)d_in[13];
    const float* lnf_g     = (const float*)d_in[14];
    const float* lnf_bp    = (const float*)d_in[15];

    float *p_out, *p_tmp;
    __nv_bfloat16 *p_whi, *p_wlo, *p_ahi, *p_alo, *p_hhi, *p_hlo, *p_qkvh;
    unsigned char* p_kpm;
    cudaGetSymbolAddress((void**)&p_out,  g_out);
    cudaGetSymbolAddress((void**)&p_tmp,  g_tmp);
    cudaGetSymbolAddress((void**)&p_whi,  g_whib);
    cudaGetSymbolAddress((void**)&p_wlo,  g_wlob);
    cudaGetSymbolAddress((void**)&p_ahi,  g_ahib);
    cudaGetSymbolAddress((void**)&p_alo,  g_alob);
    cudaGetSymbolAddress((void**)&p_hhi,  g_hhib);
    cudaGetSymbolAddress((void**)&p_hlo,  g_hlob);
    cudaGetSymbolAddress((void**)&p_qkvh, g_qkvh);
    cudaGetSymbolAddress((void**)&p_kpm,  g_kpm);

    cudaFuncSetAttribute(hmma_gemm<false,false>, cudaFuncAttributeMaxDynamicSharedMemorySize, GSM_TOTAL);
    cudaFuncSetAttribute(hmma_gemm<false,true>,  cudaFuncAttributeMaxDynamicSharedMemorySize, GSM_TOTAL);
    cudaFuncSetAttribute(hmma_gemm<true,true>,   cudaFuncAttributeMaxDynamicSharedMemorySize, GSM_TOTAL);
    cudaFuncSetAttribute(attn_mma, cudaFuncAttributeMaxDynamicSharedMemorySize, ASM_TOTAL);

    kpm_kernel<<<MM, 128>>>(x, p_kpm);
    {
        int n4 = MM * DV / 4;
        copy_split_kernel<<<(n4 + 255) / 256, 256>>>(x, p_out, p_ahi, p_alo, n4);
    }

    // split weights once
    {
        int n4;
        n4 = W_IN_SZ  / 4; splitb_kernel<<<(n4 + 255) / 256, 256>>>(in_proj_w, p_whi + OFF_IN,  p_wlo + OFF_IN,  n4);
        n4 = W_OUT_SZ / 4; splitb_kernel<<<(n4 + 255) / 256, 256>>>(out_w,     p_whi + OFF_OUT, p_wlo + OFF_OUT, n4);
        n4 = W_L1_SZ  / 4; splitb_kernel<<<(n4 + 255) / 256, 256>>>(lin1_w,    p_whi + OFF_L1,  p_wlo + OFF_L1,  n4);
        n4 = W_L2_SZ  / 4; splitb_kernel<<<(n4 + 255) / 256, 256>>>(lin2_w,    p_whi + OFF_L2,  p_wlo + OFF_L2,  n4);
    }

    for (int l = 0; l < NLAYER; l++) {
        const __nv_bfloat16* whi_in = p_whi + OFF_IN  + (size_t)l * 3 * DV * DV;
        const __nv_bfloat16* wlo_in = p_wlo + OFF_IN  + (size_t)l * 3 * DV * DV;
        const __nv_bfloat16* whi_o  = p_whi + OFF_OUT + (size_t)l * DV * DV;
        const __nv_bfloat16* wlo_o  = p_wlo + OFF_OUT + (size_t)l * DV * DV;
        const __nv_bfloat16* whi_1  = p_whi + OFF_L1  + (size_t)l * DFF * DV;
        const __nv_bfloat16* wlo_1  = p_wlo + OFF_L1  + (size_t)l * DFF * DV;
        const __nv_bfloat16* whi_2  = p_whi + OFF_L2  + (size_t)l * DV * DFF;
        const __nv_bfloat16* wlo_2  = p_wlo + OFF_L2  + (size_t)l * DV * DFF;
        const float* bq  = in_proj_b + (size_t)l * 3 * DV;
        const float* bo  = out_b     + (size_t)l * DV;
        const float* b1  = lin1_b    + (size_t)l * DFF;
        const float* b2  = lin2_b    + (size_t)l * DV;

        // QKV projection -> single-bf16 qkv (hi only)
        hmma_gemm<false,true><<<dim3(3 * DV / 128, MM / 128), 256, GSM_TOTAL>>>(
            p_ahi, p_alo, whi_in, wlo_in, bq, nullptr, p_qkvh, nullptr, 3 * DV, DV);
        // mma flash attention -> attn activation as hi/lo bf16
        attn_mma<<<dim3(BB * NH, LL / 128), 256, ASM_TOTAL>>>(
            p_qkvh, dist_emb, p_kpm, p_ahi, p_alo);
        // output projection
        hmma_gemm<false,false><<<dim3(DV / 128, MM / 128), 256, GSM_TOTAL>>>(
            p_ahi, p_alo, whi_o, wlo_o, bo, p_tmp, nullptr, nullptr, DV, DV);
        // residual + LN1 -> fp32 + hi/lo
        ln_kernel<<<MM, 128>>>(p_out, p_tmp, ln1_g + (size_t)l * DV, ln1_bp + (size_t)l * DV,
                               p_out, p_ahi, p_alo);
        // FFN up: gelu epilogue writes hi/lo directly
        hmma_gemm<true,true><<<dim3(DFF / 128, MM / 128), 256, GSM_TOTAL>>>(
            p_ahi, p_alo, whi_1, wlo_1, b1, nullptr, p_hhi, p_hlo, DFF, DV);
        // FFN down
        hmma_gemm<false,false><<<dim3(DV / 128, MM / 128), 256, GSM_TOTAL>>>(
            p_hhi, p_hlo, whi_2, wlo_2, b2, p_tmp, nullptr, nullptr, DV, DFF);
        // residual + LN2 -> fp32 + hi/lo (next layer's GEMM input)
        ln_kernel<<<MM, 128>>>(p_out, p_tmp, ln2_g + (size_t)l * DV, ln2_bp + (size_t)l * DV,
                               p_out, p_ahi, p_alo);
    }

    ln_kernel<<<MM, 128>>>(p_out, (const float*)nullptr, lnf_g, lnf_bp, (float*)d_out,
                           nullptr, nullptr);
}

// round 16
// speedup vs baseline: 1.2080x; 1.1148x over previous
#include <cuda_runtime.h>
#include <cuda_bf16.h>
#include <math.h>
#include <cstdint>

#define NLAYER 6
#define DV     512
#define NH     8
#define HD     64
#define DFF    2048
#define BB     8
#define LL     1024
#define MM     (BB*LL)
#define QKV_STRIDE (3*DV)

// ---------------- scratch ----------------
__device__ float g_out [MM*DV];
__device__ float g_tmp [MM*DV];
__device__ unsigned char g_kpm[MM];

#define W_IN_SZ   (NLAYER*3*DV*DV)
#define W_OUT_SZ  (NLAYER*DV*DV)
#define W_L1_SZ   (NLAYER*DFF*DV)
#define W_L2_SZ   (NLAYER*DV*DFF)
#define W_TOT     (W_IN_SZ+W_OUT_SZ+W_L1_SZ+W_L2_SZ)
#define OFF_IN    0
#define OFF_OUT   (W_IN_SZ)
#define OFF_L1    (W_IN_SZ+W_OUT_SZ)
#define OFF_L2    (W_IN_SZ+W_OUT_SZ+W_L1_SZ)
__device__ __nv_bfloat16 g_whib[W_TOT];
__device__ __nv_bfloat16 g_wlob[W_TOT];
__device__ __nv_bfloat16 g_ahib[MM*DFF];
__device__ __nv_bfloat16 g_alob[MM*DFF];
__device__ __nv_bfloat16 g_hhib[MM*DFF];
__device__ __nv_bfloat16 g_hlob[MM*DFF];
__device__ __nv_bfloat16 g_qkvh[MM*3*DV];

// ---------------- smem / mma helpers ----------------
__device__ __forceinline__ uint32_t s2u(const void* p) {
    uint32_t a;
    asm("{ .reg .u64 t; cvta.to.shared.u64 t, %1; cvt.u32.u64 %0, t; }" : "=r"(a) : "l"(p));
    return a;
}
__device__ __forceinline__ void cpa16(uint32_t dst, const void* src) {
    asm volatile("cp.async.cg.shared.global [%0], [%1], 16;" :: "r"(dst), "l"(src) : "memory");
}
__device__ __forceinline__ void cpa_commit() { asm volatile("cp.async.commit_group;" ::: "memory"); }
__device__ __forceinline__ void cpa_wait0() { asm volatile("cp.async.wait_group 0;" ::: "memory"); }
__device__ __forceinline__ void cpa_wait1() { asm volatile("cp.async.wait_group 1;" ::: "memory"); }
__device__ __forceinline__ void ldmx4(uint32_t* r, uint32_t addr) {
    asm volatile("ldmatrix.sync.aligned.m8n8.x4.shared.b16 {%0,%1,%2,%3}, [%4];"
        : "=r"(r[0]), "=r"(r[1]), "=r"(r[2]), "=r"(r[3]) : "r"(addr));
}
__device__ __forceinline__ void ldmx4t(uint32_t* r, uint32_t addr) {
    asm volatile("ldmatrix.sync.aligned.m8n8.x4.trans.shared.b16 {%0,%1,%2,%3}, [%4];"
        : "=r"(r[0]), "=r"(r[1]), "=r"(r[2]), "=r"(r[3]) : "r"(addr));
}
__device__ __forceinline__ void mma_bf16(float* d, const uint32_t* a, const uint32_t* b) {
    asm volatile("mma.sync.aligned.m16n8k16.row.col.f32.bf16.bf16.f32 "
        "{%0,%1,%2,%3}, {%4,%5,%6,%7}, {%8,%9}, {%0,%1,%2,%3};"
        : "+f"(d[0]), "+f"(d[1]), "+f"(d[2]), "+f"(d[3])
        : "r"(a[0]), "r"(a[1]), "r"(a[2]), "r"(a[3]), "r"(b[0]), "r"(b[1]));
}
__device__ __forceinline__ float ex2f(float x) {
    float r;
    asm("ex2.approx.f32 %0, %1;" : "=f"(r) : "f"(x));
    return r;
}
__device__ __forceinline__ uint32_t cvt1(float x0, float x1) {
    uint32_t p;
    asm("cvt.rn.bf16x2.f32 %0, %1, %2;" : "=r"(p) : "f"(x1), "f"(x0));
    return p;
}

// hi/lo bf16x2 pair from two floats (x0 -> low half)
#define CVTPAIR(dsthi, dstlo, x0, x1) do { \
    uint32_t _hp; asm("cvt.rn.bf16x2.f32 %0, %1, %2;" : "=r"(_hp) : "f"(x1), "f"(x0)); \
    float _h0 = __uint_as_float(_hp << 16); \
    float _h1 = __uint_as_float(_hp & 0xFFFF0000u); \
    uint32_t _lp; asm("cvt.rn.bf16x2.f32 %0, %1, %2;" : "=r"(_lp) : "f"((x1) - _h1), "f"((x0) - _h0)); \
    (dsthi) = _hp; (dstlo) = _lp; } while(0)

// ---------------- key padding mask ----------------
__global__ void kpm_kernel(const float* __restrict__ x, unsigned char* __restrict__ kpm)
{
    int row = blockIdx.x;
    int t = threadIdx.x;
    int nz = 0;
    for (int c = t; c < DV; c += 128)
        nz |= (x[(size_t)row * DV + c] != 0.0f) ? 1 : 0;
    nz = __syncthreads_or(nz);
    if (t == 0) kpm[row] = nz ? 0 : 1;
}

// ---------------- copy + hi/lo split (initial x) ----------------
__global__ void copy_split_kernel(const float* __restrict__ src, float* __restrict__ dst,
                                  __nv_bfloat16* __restrict__ hi, __nv_bfloat16* __restrict__ lo, int n4)
{
    int i = blockIdx.x * blockDim.x + threadIdx.x;
    if (i >= n4) return;
    float4 v = ((const float4*)src)[i];
    ((float4*)dst)[i] = v;
    __nv_bfloat16 h0 = __float2bfloat16_rn(v.x), h1 = __float2bfloat16_rn(v.y);
    __nv_bfloat16 h2 = __float2bfloat16_rn(v.z), h3 = __float2bfloat16_rn(v.w);
    __nv_bfloat162* hp = (__nv_bfloat162*)hi;
    __nv_bfloat162* lp = (__nv_bfloat162*)lo;
    hp[2*i]   = __nv_bfloat162(h0, h1);
    hp[2*i+1] = __nv_bfloat162(h2, h3);
    lp[2*i]   = __nv_bfloat162(__float2bfloat16_rn(v.x - __bfloat162float(h0)),
                               __float2bfloat16_rn(v.y - __bfloat162float(h1)));
    lp[2*i+1] = __nv_bfloat162(__float2bfloat16_rn(v.z - __bfloat162float(h2)),
                               __float2bfloat16_rn(v.w - __bfloat162float(h3)));
}

// ---------------- weight hi/lo split ----------------
__global__ void splitb_kernel(const float* __restrict__ src,
                              __nv_bfloat16* __restrict__ hi,
                              __nv_bfloat16* __restrict__ lo, int n4)
{
    int i = blockIdx.x * blockDim.x + threadIdx.x;
    if (i >= n4) return;
    float4 v = ((const float4*)src)[i];
    __nv_bfloat16 h0 = __float2bfloat16_rn(v.x), h1 = __float2bfloat16_rn(v.y);
    __nv_bfloat16 h2 = __float2bfloat16_rn(v.z), h3 = __float2bfloat16_rn(v.w);
    __nv_bfloat162* hp = (__nv_bfloat162*)hi;
    __nv_bfloat162* lp = (__nv_bfloat162*)lo;
    hp[2*i]   = __nv_bfloat162(h0, h1);
    hp[2*i+1] = __nv_bfloat162(h2, h3);
    lp[2*i]   = __nv_bfloat162(__float2bfloat16_rn(v.x - __bfloat162float(h0)),
                               __float2bfloat16_rn(v.y - __bfloat162float(h1)));
    lp[2*i+1] = __nv_bfloat162(__float2bfloat16_rn(v.z - __bfloat162float(h2)),
                               __float2bfloat16_rn(v.w - __bfloat162float(h3)));
}

// ---------------- HMMA bf16 GEMM (3-stage cp.async, 1 barrier/chunk) ----------------
// ONETERM=false: 3-term hi/lo (fp32-accurate). ONETERM=true: Ahi*Whi only
// (used for QKV whose output is truncated to bf16 anyway); stage is 16KB.
#define GSM_STAGE3 32768
#define GSM_STAGE1 16384
#define GSM_TOTAL3 (3*GSM_STAGE3)
#define GSM_TOTAL1 (3*GSM_STAGE1)

__device__ __forceinline__ uint32_t swz(int row, int kch) {
    return (uint32_t)(row * 64 + (((kch + ((row >> 1) & 3)) & 3) << 4));
}

template<bool GELU, bool SPLIT, bool ONETERM>
__global__ __launch_bounds__(256) void hmma_gemm(
    const __nv_bfloat16* __restrict__ Ahi, const __nv_bfloat16* __restrict__ Alo,
    const __nv_bfloat16* __restrict__ Whi, const __nv_bfloat16* __restrict__ Wlo,
    const float* __restrict__ bias, float* __restrict__ C,
    __nv_bfloat16* __restrict__ Chi, __nv_bfloat16* __restrict__ Clo,
    int N, int K)
{
    extern __shared__ __align__(16) char sm[];
    const uint32_t sb = s2u(sm);
    const int t = threadIdx.x;
    const int bm = blockIdx.y * 128, bn = blockIdx.x * 128;
    const int w = t >> 5, l = t & 31;
    const int wm = w & 3, wn = w >> 2;
    constexpr uint32_t STG_SZ = ONETERM ? GSM_STAGE1 : GSM_STAGE3;
    constexpr uint32_t WOFF   = ONETERM ? 8192 : 16384;   // W-hi offset within stage

    float acc[2][8][4];
#pragma unroll
    for (int mt = 0; mt < 2; mt++)
#pragma unroll
        for (int nt = 0; nt < 8; nt++)
#pragma unroll
            for (int e = 0; e < 4; e++) acc[mt][nt][e] = 0.0f;

    const int nch = K >> 5;

    auto load_stage = [&](int stage, int kt) {
        const uint32_t base = sb + stage * STG_SZ;
        const int k0 = kt << 5;
#pragma unroll
        for (int q = 0; q < 2; q++) {
            int ch = t + (q << 8);
            int row = ch >> 2, c = ch & 3;
            uint32_t so = swz(row, c);
            size_t ga = (size_t)(bm + row) * K + k0 + c * 8;
            size_t gb = (size_t)(bn + row) * K + k0 + c * 8;
            cpa16(base + so,        Ahi + ga);
            cpa16(base + WOFF + so, Whi + gb);
            if (!ONETERM) {
                cpa16(base + 8192 + so,  Alo + ga);
                cpa16(base + 24576 + so, Wlo + gb);
            }
        }
        cpa_commit();
    };

    load_stage(0, 0);
    load_stage(1, 1);

    int stg = 0;
    for (int c = 0; c < nch; ++c) {
        if (c + 1 < nch) cpa_wait1(); else cpa_wait0();
        __syncthreads();
        if (c + 2 < nch) {
            int ns = stg + 2; if (ns >= 3) ns -= 3;
            load_stage(ns, c + 2);
        }

        const uint32_t base = sb + stg * STG_SZ;
#pragma unroll
        for (int kk = 0; kk < 2; kk++) {
            uint32_t ah[2][4], al[2][4];
#pragma unroll
            for (int mt = 0; mt < 2; mt++) {
                int row = wm * 32 + mt * 16 + (l & 15);
                int kch = kk * 2 + (l >> 4);
                uint32_t off = swz(row, kch);
                ldmx4(ah[mt], base + off);
                if (!ONETERM) ldmx4(al[mt], base + 8192 + off);
            }
            uint32_t bh[8][2], bl[8][2];
#pragma unroll
            for (int nt2 = 0; nt2 < 4; nt2++) {
                int row = wn * 64 + nt2 * 16 + (l & 7) + ((l >> 4) << 3);
                int kch = kk * 2 + ((l >> 3) & 1);
                uint32_t off = swz(row, kch);
                uint32_t r[4];
                ldmx4(r, base + WOFF + off);
                bh[nt2*2][0] = r[0]; bh[nt2*2][1] = r[1];
                bh[nt2*2+1][0] = r[2]; bh[nt2*2+1][1] = r[3];
                if (!ONETERM) {
                    ldmx4(r, base + 24576 + off);
                    bl[nt2*2][0] = r[0]; bl[nt2*2][1] = r[1];
                    bl[nt2*2+1][0] = r[2]; bl[nt2*2+1][1] = r[3];
                }
            }
#pragma unroll
            for (int mt = 0; mt < 2; mt++)
#pragma unroll
                for (int nt = 0; nt < 8; nt++) {
                    mma_bf16(acc[mt][nt], ah[mt], bh[nt]);
                    if (!ONETERM) {
                        mma_bf16(acc[mt][nt], ah[mt], bl[nt]);
                        mma_bf16(acc[mt][nt], al[mt], bh[nt]);
                    }
                }
        }
        if (++stg >= 3) stg = 0;
    }

#pragma unroll
    for (int mt = 0; mt < 2; mt++) {
        int row = bm + wm * 32 + mt * 16 + (l >> 2);
#pragma unroll
        for (int nt = 0; nt < 8; nt++) {
            int col = bn + wn * 64 + nt * 8 + 2 * (l & 3);
            float b0 = bias[col], b1 = bias[col + 1];
            float v0 = acc[mt][nt][0] + b0;
            float v1 = acc[mt][nt][1] + b1;
            float v2 = acc[mt][nt][2] + b0;
            float v3 = acc[mt][nt][3] + b1;
            if (GELU) {
                v0 = 0.5f * v0 * (1.0f + erff(v0 * 0.70710678118654752f));
                v1 = 0.5f * v1 * (1.0f + erff(v1 * 0.70710678118654752f));
                v2 = 0.5f * v2 * (1.0f + erff(v2 * 0.70710678118654752f));
                v3 = 0.5f * v3 * (1.0f + erff(v3 * 0.70710678118654752f));
            }
            if (SPLIT) {
                if (Clo) {
                    uint32_t hp, lp;
                    CVTPAIR(hp, lp, v0, v1);
                    *(uint32_t*)(Chi + (size_t)row * N + col) = hp;
                    *(uint32_t*)(Clo + (size_t)row * N + col) = lp;
                    CVTPAIR(hp, lp, v2, v3);
                    *(uint32_t*)(Chi + (size_t)(row + 8) * N + col) = hp;
                    *(uint32_t*)(Clo + (size_t)(row + 8) * N + col) = lp;
                } else {
                    *(uint32_t*)(Chi + (size_t)row * N + col)       = cvt1(v0, v1);
                    *(uint32_t*)(Chi + (size_t)(row + 8) * N + col) = cvt1(v2, v3);
                }
            } else {
                *(float2*)(C + (size_t)row * N + col)       = make_float2(v0, v1);
                *(float2*)(C + (size_t)(row + 8) * N + col) = make_float2(v2, v3);
            }
        }
    }
}

// ---------------- mma.sync flash attention ----------------
// Single-bf16 Q, K, V, P: S = qh*kh, O += ph*vh. 64 MMAs/tile.
// smem: stages 0/1/2 at 0/16384/32768 (each: Kh @0, Vh @8192);
// sbias(log2e) @49152 (4KB), smask @53248 (4KB). Q staged in stage0 first.
#define ASM_TOTAL 57344

__global__ __launch_bounds__(256, 1) void attn_mma(
    const __nv_bfloat16* __restrict__ qkvh,
    const float* __restrict__ dist_emb, const unsigned char* __restrict__ kpm,
    __nv_bfloat16* __restrict__ ohi, __nv_bfloat16* __restrict__ olo)
{
    extern __shared__ __align__(16) char sm[];
    const uint32_t sb0 = s2u(sm);
    const int bh = blockIdx.x;
    const int b = bh >> 3, h = bh & 7;
    const int qbi = (int)gridDim.y - 1 - (int)blockIdx.y;   // long blocks first
    const int qbase = qbi * 128;
    const int t = threadIdx.x;
    const int w = t >> 5, l = t & 31;

    const float LOG2E = 1.4426950408889634f;
    float* sbias = (float*)(sm + 49152);
    float* smask = (float*)(sm + 53248);
    for (int d = t; d < LL; d += 256) {
        sbias[d] = dist_emb[d * NH + h] * LOG2E;
        smask[d] = kpm[b * LL + d] ? -2e30f : 0.0f;
    }

    // stage Q (hi only @ 0)
#pragma unroll
    for (int q = 0; q < 4; q++) {
        int c = t + q * 256;
        int row = c >> 3, ch = c & 7;
        size_t g = (size_t)(b * LL + qbase + row) * QKV_STRIDE + h * HD + ch * 8;
        uint32_t off = (uint32_t)(row * 128 + ((ch ^ (row & 7)) << 4));
        cpa16(sb0 + off, qkvh + g);
    }
    cpa_commit();
    cpa_wait0();
    __syncthreads();

    uint32_t qh[4][4];
    {
        int qrow = w * 16 + (l & 15);
#pragma unroll
        for (int j = 0; j < 4; j++) {
            int ch = 2 * j + (l >> 4);
            uint32_t addr = sb0 + qrow * 128 + ((ch ^ (qrow & 7)) << 4);
            ldmx4(qh[j], addr);
        }
    }
    __syncthreads();   // Q extracted before K/V overwrite

    float o[8][4];
#pragma unroll
    for (int dt = 0; dt < 8; dt++)
#pragma unroll
        for (int e = 0; e < 4; e++) o[dt][e] = 0.0f;
    float ls0 = 0.0f, ls1 = 0.0f;
    const int i0 = qbase + w * 16 + (l >> 2);
    const int i1 = i0 + 8;
    const int ntile = (qbase + 128) >> 6;

    auto load_kv = [&](int stage, int jt) {
        const uint32_t base = sb0 + stage * 16384;
#pragma unroll
        for (int q = 0; q < 2; q++) {
            int c = t + q * 256;
            int row = c >> 3, ch = c & 7;
            size_t gk = (size_t)(b * LL + jt + row) * QKV_STRIDE + DV + h * HD + ch * 8;
            size_t gv = gk + DV;
            uint32_t off = (uint32_t)(row * 128 + ((ch ^ (row & 7)) << 4));
            cpa16(base + off,        qkvh + gk);
            cpa16(base + 8192 + off, qkvh + gv);
        }
        cpa_commit();
    };

    load_kv(0, 0);
    if (ntile > 1) load_kv(1, 64);

    int stg = 0;
    for (int ti = 0; ti < ntile; ti++) {
        if (ti + 1 < ntile) cpa_wait1(); else cpa_wait0();
        __syncthreads();
        if (ti + 2 < ntile) {
            int ns = stg + 2; if (ns >= 3) ns -= 3;
            load_kv(ns, (ti + 2) << 6);
        }

        const int jt = ti << 6;
        if (jt <= qbase + w * 16 + 15) {
            const uint32_t kb = sb0 + stg * 16384;

            // ---- S = Qh Kh^T ----
            float s[8][4];
#pragma unroll
            for (int nt = 0; nt < 8; nt++)
#pragma unroll
                for (int e = 0; e < 4; e++) s[nt][e] = 0.0f;

            const int krow = (l & 7) + ((l >> 4) << 3);
#pragma unroll
            for (int kc = 0; kc < 4; kc++) {
                const int kch = 2 * kc + ((l >> 3) & 1);
#pragma unroll
                for (int nt2 = 0; nt2 < 4; nt2++) {
                    int row = nt2 * 16 + krow;
                    uint32_t addr = kb + row * 128 + ((kch ^ (row & 7)) << 4);
                    uint32_t rh[4];
                    ldmx4(rh, addr);
                    uint32_t b0h[2] = {rh[0], rh[1]}, b1h[2] = {rh[2], rh[3]};
                    mma_bf16(s[nt2*2],   qh[kc], b0h);
                    mma_bf16(s[nt2*2+1], qh[kc], b1h);
                }
            }

            // ---- scale(log2) + bias + causal/kpm mask, direct exp2 ----
            const float scale2 = 0.125f * LOG2E;
            const int jc = jt + 2 * (l & 3);
#pragma unroll
            for (int nt = 0; nt < 8; nt++) {
                int j0 = jc + nt * 8;
                float mk0 = smask[j0], mk1 = smask[j0 + 1];
                int d0 = i0 - j0;
                int d1 = i1 - j0;
                s[nt][0] = (d0 >= 0) ? ex2f(fmaf(s[nt][0], scale2, sbias[d0]     + mk0)) : 0.0f;
                s[nt][1] = (d0 >= 1) ? ex2f(fmaf(s[nt][1], scale2, sbias[d0 - 1] + mk1)) : 0.0f;
                s[nt][2] = (d1 >= 0) ? ex2f(fmaf(s[nt][2], scale2, sbias[d1]     + mk0)) : 0.0f;
                s[nt][3] = (d1 >= 1) ? ex2f(fmaf(s[nt][3], scale2, sbias[d1 - 1] + mk1)) : 0.0f;
                ls0 += s[nt][0] + s[nt][1];
                ls1 += s[nt][2] + s[nt][3];
            }

            // ---- P -> single-bf16 A-fragments ----
            uint32_t ph[4][4];
#pragma unroll
            for (int j = 0; j < 4; j++) {
                ph[j][0] = cvt1(s[2*j][0],   s[2*j][1]);
                ph[j][1] = cvt1(s[2*j][2],   s[2*j][3]);
                ph[j][2] = cvt1(s[2*j+1][0], s[2*j+1][1]);
                ph[j][3] = cvt1(s[2*j+1][2], s[2*j+1][3]);
            }

            // ---- O += Ph Vh ----
            const int vsub = (l & 7) + (((l >> 3) & 1) << 3);
#pragma unroll
            for (int j = 0; j < 4; j++) {
                int vrow = j * 16 + vsub;
#pragma unroll
                for (int dp = 0; dp < 4; dp++) {
                    int ch = 2 * dp + (l >> 4);
                    uint32_t addr = kb + 8192 + vrow * 128 + ((ch ^ (vrow & 7)) << 4);
                    uint32_t rh[4];
                    ldmx4t(rh, addr);
                    uint32_t v0h[2] = {rh[0], rh[1]}, v1h[2] = {rh[2], rh[3]};
                    mma_bf16(o[2*dp],   ph[j], v0h);
                    mma_bf16(o[2*dp+1], ph[j], v1h);
                }
            }
        }
        if (++stg >= 3) stg = 0;
    }

    // ---- finalize ----
    ls0 += __shfl_xor_sync(0xFFFFFFFFu, ls0, 1);
    ls0 += __shfl_xor_sync(0xFFFFFFFFu, ls0, 2);
    ls1 += __shfl_xor_sync(0xFFFFFFFFu, ls1, 1);
    ls1 += __shfl_xor_sync(0xFFFFFFFFu, ls1, 2);
    float inv0 = 1.0f / ls0, inv1 = 1.0f / ls1;

#pragma unroll
    for (int dt = 0; dt < 8; dt++) {
        int col = h * HD + dt * 8 + 2 * (l & 3);
        size_t r0 = (size_t)(b * LL + i0) * DV + col;
        size_t r1 = (size_t)(b * LL + i1) * DV + col;
        uint32_t hp, lp;
        CVTPAIR(hp, lp, o[dt][0] * inv0, o[dt][1] * inv0);
        *(uint32_t*)(ohi + r0) = hp;
        *(uint32_t*)(olo + r0) = lp;
        CVTPAIR(hp, lp, o[dt][2] * inv1, o[dt][3] * inv1);
        *(uint32_t*)(ohi + r1) = hp;
        *(uint32_t*)(olo + r1) = lp;
    }
}

// ---------------- residual + LayerNorm (float4, optional bf16 hi/lo out) ----------------
__global__ __launch_bounds__(128) void ln_kernel(
    const float* __restrict__ x, const float* __restrict__ res,
    const float* __restrict__ g, const float* __restrict__ beta,
    float* __restrict__ outp,
    __nv_bfloat16* __restrict__ ohi, __nv_bfloat16* __restrict__ olo)
{
    const int row = blockIdx.x;
    const int t = threadIdx.x;
    const size_t base = (size_t)row * DV + 4 * t;

    float4 v = *(const float4*)(x + base);
    if (res) {
        float4 rv = *(const float4*)(res + base);
        v.x += rv.x; v.y += rv.y; v.z += rv.z; v.w += rv.w;
    }
    float s  = v.x + v.y + v.z + v.w;
    float ss = v.x * v.x + v.y * v.y + v.z * v.z + v.w * v.w;
#pragma unroll
    for (int o = 16; o > 0; o >>= 1) {
        s  += __shfl_xor_sync(0xFFFFFFFFu, s,  o);
        ss += __shfl_xor_sync(0xFFFFFFFFu, ss, o);
    }
    __shared__ float rs[4], rss[4];
    int w = t >> 5;
    if ((t & 31) == 0) { rs[w] = s; rss[w] = ss; }
    __syncthreads();
    s  = rs[0] + rs[1] + rs[2] + rs[3];
    ss = rss[0] + rss[1] + rss[2] + rss[3];
    float mean = s * (1.0f / DV);
    float var  = ss * (1.0f / DV) - mean * mean;
    float r = rsqrtf(var + 1e-5f);

    float4 gv = *(const float4*)(g + 4 * t);
    float4 bv = *(const float4*)(beta + 4 * t);
    float4 ov;
    ov.x = (v.x - mean) * r * gv.x + bv.x;
    ov.y = (v.y - mean) * r * gv.y + bv.y;
    ov.z = (v.z - mean) * r * gv.z + bv.z;
    ov.w = (v.w - mean) * r * gv.w + bv.w;
    *(float4*)(outp + base) = ov;
    if (ohi) {
        uint32_t hp, lp;
        CVTPAIR(hp, lp, ov.x, ov.y);
        *(uint32_t*)(ohi + base) = hp;
        *(uint32_t*)(olo + base) = lp;
        CVTPAIR(hp, lp, ov.z, ov.w);
        *(uint32_t*)(ohi + base + 2) = hp;
        *(uint32_t*)(olo + base + 2) = lp;
    }
}

// ---------------- host launcher ----------------
extern "C" void kernel_launch(void* const* d_in, const int* in_sizes, int n_in,
                              void* d_out, int out_size)
{
    (void)in_sizes; (void)n_in; (void)out_size;
    const float* x         = (const float*)d_in[0];
    const float* dist_emb  = (const float*)d_in[1];
    const float* in_proj_w = (const float*)d_in[2];
    const float* in_proj_b = (const float*)d_in[3];
    const float* out_w     = (const float*)d_in[4];
    const float* out_b     = (const float*)d_in[5];
    const float* lin1_w    = (const float*)d_in[6];
    const float* lin1_b    = (const float*)d_in[7];
    const float* lin2_w    = (const float*)d_in[8];
    const float* lin2_b    = (const float*)d_in[9];
    const float* ln1_g     = (const float*)d_in[10];
    const float* ln1_bp    = (const float*)d_in[11];
    const float* ln2_g     = (const float*)d_in[12];
    const float* ln2_bp    = (const float*)d_in[13];
    const float* lnf_g     = (const float*)d_in[14];
    const float* lnf_bp    = (const float*)d_in[15];

    float *p_out, *p_tmp;
    __nv_bfloat16 *p_whi, *p_wlo, *p_ahi, *p_alo, *p_hhi, *p_hlo, *p_qkvh;
    unsigned char* p_kpm;
    cudaGetSymbolAddress((void**)&p_out,  g_out);
    cudaGetSymbolAddress((void**)&p_tmp,  g_tmp);
    cudaGetSymbolAddress((void**)&p_whi,  g_whib);
    cudaGetSymbolAddress((void**)&p_wlo,  g_wlob);
    cudaGetSymbolAddress((void**)&p_ahi,  g_ahib);
    cudaGetSymbolAddress((void**)&p_alo,  g_alob);
    cudaGetSymbolAddress((void**)&p_hhi,  g_hhib);
    cudaGetSymbolAddress((void**)&p_hlo,  g_hlob);
    cudaGetSymbolAddress((void**)&p_qkvh, g_qkvh);
    cudaGetSymbolAddress((void**)&p_kpm,  g_kpm);

    cudaFuncSetAttribute(hmma_gemm<false,false,false>, cudaFuncAttributeMaxDynamicSharedMemorySize, GSM_TOTAL3);
    cudaFuncSetAttribute(hmma_gemm<false,true,true>,   cudaFuncAttributeMaxDynamicSharedMemorySize, GSM_TOTAL1);
    cudaFuncSetAttribute(hmma_gemm<true,true,false>,   cudaFuncAttributeMaxDynamicSharedMemorySize, GSM_TOTAL3);
    cudaFuncSetAttribute(attn_mma, cudaFuncAttributeMaxDynamicSharedMemorySize, ASM_TOTAL);

    kpm_kernel<<<MM, 128>>>(x, p_kpm);
    {
        int n4 = MM * DV / 4;
        copy_split_kernel<<<(n4 + 255) / 256, 256>>>(x, p_out, p_ahi, p_alo, n4);
    }

    // split weights once
    {
        int n4;
        n4 = W_IN_SZ  / 4; splitb_kernel<<<(n4 + 255) / 256, 256>>>(in_proj_w, p_whi + OFF_IN,  p_wlo + OFF_IN,  n4);
        n4 = W_OUT_SZ / 4; splitb_kernel<<<(n4 + 255) / 256, 256>>>(out_w,     p_whi + OFF_OUT, p_wlo + OFF_OUT, n4);
        n4 = W_L1_SZ  / 4; splitb_kernel<<<(n4 + 255) / 256, 256>>>(lin1_w,    p_whi + OFF_L1,  p_wlo + OFF_L1,  n4);
        n4 = W_L2_SZ  / 4; splitb_kernel<<<(n4 + 255) / 256, 256>>>(lin2_w,    p_whi + OFF_L2,  p_wlo + OFF_L2,  n4);
    }

    for (int l = 0; l < NLAYER; l++) {
        const __nv_bfloat16* whi_in = p_whi + OFF_IN  + (size_t)l * 3 * DV * DV;
        const __nv_bfloat16* whi_o  = p_whi + OFF_OUT + (size_t)l * DV * DV;
        const __nv_bfloat16* wlo_o  = p_wlo + OFF_OUT + (size_t)l * DV * DV;
        const __nv_bfloat16* whi_1  = p_whi + OFF_L1  + (size_t)l * DFF * DV;
        const __nv_bfloat16* wlo_1  = p_wlo + OFF_L1  + (size_t)l * DFF * DV;
        const __nv_bfloat16* whi_2  = p_whi + OFF_L2  + (size_t)l * DV * DFF;
        const __nv_bfloat16* wlo_2  = p_wlo + OFF_L2  + (size_t)l * DV * DFF;
        const float* bq  = in_proj_b + (size_t)l * 3 * DV;
        const float* bo  = out_b     + (size_t)l * DV;
        const float* b1  = lin1_b    + (size_t)l * DFF;
        const float* b2  = lin2_b    + (size_t)l * DV;

        // QKV projection: 1-term (output is bf16-truncated anyway)
        hmma_gemm<false,true,true><<<dim3(3 * DV / 128, MM / 128), 256, GSM_TOTAL1>>>(
            p_ahi, nullptr, whi_in, nullptr, bq, nullptr, p_qkvh, nullptr, 3 * DV, DV);
        // mma flash attention -> attn activation as hi/lo bf16
        attn_mma<<<dim3(BB * NH, LL / 128), 256, ASM_TOTAL>>>(
            p_qkvh, dist_emb, p_kpm, p_ahi, p_alo);
        // output projection (3-term)
        hmma_gemm<false,false,false><<<dim3(DV / 128, MM / 128), 256, GSM_TOTAL3>>>(
            p_ahi, p_alo, whi_o, wlo_o, bo, p_tmp, nullptr, nullptr, DV, DV);
        // residual + LN1 -> fp32 + hi/lo
        ln_kernel<<<MM, 128>>>(p_out, p_tmp, ln1_g + (size_t)l * DV, ln1_bp + (size_t)l * DV,
                               p_out, p_ahi, p_alo);
        // FFN up: gelu epilogue writes hi/lo (3-term)
        hmma_gemm<true,true,false><<<dim3(DFF / 128, MM / 128), 256, GSM_TOTAL3>>>(
            p_ahi, p_alo, whi_1, wlo_1, b1, nullptr, p_hhi, p_hlo, DFF, DV);
        // FFN down (3-term)
        hmma_gemm<false,false,false><<<dim3(DV / 128, MM / 128), 256, GSM_TOTAL3>>>(
            p_hhi, p_hlo, whi_2, wlo_2, b2, p_tmp, nullptr, nullptr, DV, DFF);
        // residual + LN2 -> fp32 + hi/lo (next layer's GEMM input)
        ln_kernel<<<MM, 128>>>(p_out, p_tmp, ln2_g + (size_t)l * DV, ln2_bp + (size_t)l * DV,
                               p_out, p_ahi, p_alo);
    }

    ln_kernel<<<MM, 128>>>(p_out, (const float*)nullptr, lnf_g, lnf_bp, (float*)d_out,
                           nullptr, nullptr);
}